// round 4
// baseline (speedup 1.0000x reference)
#include <cuda_runtime.h>

// ---------------- problem constants ----------------
#define NNODES 139425          // 65*65*33
#define NCELLS 131072          // 64*64*32
#define NACT   81920
#define EPSD   1.0e-7f
#define ATOL2  2.0e-12         // (1e-6)^2 * ||b||^2, ||b||^2 = 2
#define NCX 137280             // 64*65*33
#define NCY 137280             // 65*64*33
#define NCZ 135200             // 65*65*32
#define CG_ITERS 100
#define NBLK 148
#define NTHR 1024

// ---------------- device scratch ----------------
__device__ float4 g_p[NNODES*4];
__device__ float4 g_r[NNODES*4];
__device__ float4 g_q[NNODES*4];
__device__ float  g_sigma[NCELLS];
__device__ float  g_cx[NCX];
__device__ float  g_cy[NCY];
__device__ float  g_cz[NCZ];
__device__ float  g_pqpart[NBLK*16];
__device__ float  g_g2part[NBLK*16];
__device__ float  g_xsel[32*16];
__device__ volatile unsigned g_arr[NBLK];
__device__ volatile unsigned g_rel;

// ---------------- setup kernels ----------------
__global__ void k_init_sigma() {
    int t = blockIdx.x*blockDim.x + threadIdx.x;
    if (t < NCELLS) g_sigma[t] = 1.0e-8f;            // 1/AIR_RES
}

__global__ void k_scatter(const int* __restrict__ act, const float* __restrict__ model) {
    int t = blockIdx.x*blockDim.x + threadIdx.x;
    if (t < NACT) g_sigma[act[t]] = 1.0f / model[t];
}

__global__ void k_coeffs() {
    int t = blockIdx.x*blockDim.x + threadIdx.x;
    if (t < NCX) {
        int k = t % 33; int r = t / 33; int j = r % 65; int i = r / 65;
        float s = 0.f;
        for (int jj = j-1; jj <= j; ++jj)
            for (int kk = k-1; kk <= k; ++kk)
                if (jj >= 0 && jj < 64 && kk >= 0 && kk < 32)
                    s += g_sigma[(i*64 + jj)*32 + kk];
        g_cx[t] = 6.25f * s;                          // 0.25 * 25.0
    } else if (t < NCX + NCY) {
        int e = t - NCX;
        int k = e % 33; int r = e / 33; int j = r % 64; int i = r / 64;
        float s = 0.f;
        for (int ii = i-1; ii <= i; ++ii)
            for (int kk = k-1; kk <= k; ++kk)
                if (ii >= 0 && ii < 64 && kk >= 0 && kk < 32)
                    s += g_sigma[(ii*64 + j)*32 + kk];
        g_cy[e] = 6.25f * s;
    } else if (t < NCX + NCY + NCZ) {
        int e = t - NCX - NCY;
        int k = e % 32; int r = e / 32; int j = r % 65; int i = r / 65;
        float s = 0.f;
        for (int ii = i-1; ii <= i; ++ii)
            for (int jj = j-1; jj <= j; ++jj)
                if (ii >= 0 && ii < 64 && jj >= 0 && jj < 64)
                    s += g_sigma[(ii*64 + jj)*32 + k];
        g_cz[e] = 6.25f * s;
    }
}

// r = b; p = 0; x-slots = 0
__global__ void k_initvec(const int* __restrict__ sa, const int* __restrict__ sb) {
    int t = blockIdx.x*blockDim.x + threadIdx.x;
    if (t < NNODES*4) {
        float4 z = make_float4(0.f,0.f,0.f,0.f);
        g_p[t] = z; g_r[t] = z;
    }
    if (t < 32*16) g_xsel[t] = 0.f;
    if (t < 16) {
        float* rf = (float*)g_r;
        rf[sa[t]*16 + t]  = 1.0f;        // distinct nodes, no race with zeros:
        rf[sb[t]*16 + t] -= 1.0f;        // (separate kernel below fixes ordering)
    }
}
// NOTE: the sa/sb writes above race with zero-fill from other threads of the
// same kernel; do them in a second tiny kernel instead.
__global__ void k_setb(const int* __restrict__ sa, const int* __restrict__ sb) {
    int s = threadIdx.x;
    if (s < 16) {
        float* rf = (float*)g_r;
        rf[sa[s]*16 + s]  = 1.0f;
        rf[sb[s]*16 + s] -= 1.0f;
    }
}

// ---------------- software grid barrier ----------------
__device__ __forceinline__ void gsync(unsigned target) {
    __syncthreads();
    if (threadIdx.x == 0) {
        __threadfence();
        g_arr[blockIdx.x] = target;
    }
    if (blockIdx.x == 0) {
        if (threadIdx.x < 32) {
            for (int b = (int)threadIdx.x; b < NBLK; b += 32) {
                while (g_arr[b] < target) { }
            }
            __syncwarp();
            if (threadIdx.x == 0) { __threadfence(); g_rel = target; }
        }
    } else {
        if (threadIdx.x == 0) {
            while (g_rel < target) { }
            __threadfence();
        }
    }
    __syncthreads();
}

// block reduction: EXPR(s) summed over the block -> gout[0..15] (float)
#define BLOCKRED(EXPR, gout)                                                   \
    {                                                                          \
        _Pragma("unroll")                                                      \
        for (int s = 0; s < 16; s++) {                                         \
            float v = (EXPR);                                                  \
            v += __shfl_down_sync(0xffffffffu, v, 16);                         \
            v += __shfl_down_sync(0xffffffffu, v, 8);                          \
            v += __shfl_down_sync(0xffffffffu, v, 4);                          \
            v += __shfl_down_sync(0xffffffffu, v, 2);                          \
            v += __shfl_down_sync(0xffffffffu, v, 1);                          \
            if (lane == 0) s_red[wid*16 + s] = v;                              \
        }                                                                      \
        __syncthreads();                                                       \
        if (tid < 16) {                                                        \
            float acc = 0.f;                                                   \
            _Pragma("unroll")                                                  \
            for (int w = 0; w < 32; w++) acc += s_red[w*16 + tid];             \
            s_cross[tid] = acc;                                                \
        }                                                                      \
        __syncthreads();                                                       \
        if (tid == 0) {                                                        \
            float4* o = (float4*)(gout);                                       \
            const float4* c = (const float4*)s_cross;                          \
            o[0] = c[0]; o[1] = c[1]; o[2] = c[2]; o[3] = c[3];                \
        }                                                                      \
    }

// one stencil direction: q += c * (p - p_neighbor)
#define NB(nb4, cval)                                                          \
    {                                                                          \
        float c_ = (cval);                                                     \
        _Pragma("unroll")                                                      \
        for (int u = 0; u < 4; u++) {                                          \
            float4 pn = g_p[(nb4) + u];                                        \
            qq[4*u+0] += c_*(pp[4*u+0] - pn.x);                                \
            qq[4*u+1] += c_*(pp[4*u+1] - pn.y);                                \
            qq[4*u+2] += c_*(pp[4*u+2] - pn.z);                                \
            qq[4*u+3] += c_*(pp[4*u+3] - pn.w);                                \
        }                                                                      \
    }

// ---------------- persistent CG kernel ----------------
__global__ void __launch_bounds__(NTHR, 1)
k_persist(const int* __restrict__ rxm, const int* __restrict__ rxn)
{
    const int tid = threadIdx.x;
    const int bid = blockIdx.x;
    const int lane = tid & 31;
    const int wid  = tid >> 5;
    const int node = bid*NTHR + tid;
    const bool valid = node < NNODES;

    int i = 0, j = 0, k = 0, base4 = 0;
    if (valid) {
        k = node % 33;
        int ij = node / 33;
        j = ij % 65;
        i = ij / 65;
        base4 = node * 4;
    }

    // receiver-slot ownership (32 distinct nodes)
    int slot = -1;
    if (valid) {
        for (int r2 = 0; r2 < 16; r2++) {
            if (node == rxm[r2]) slot = r2;
            if (node == rxn[r2]) slot = 16 + r2;
        }
    }

    __shared__ float  s_red[32*16];
    __shared__ float  s_cross[16];
    __shared__ double s_dred[64];
    __shared__ float  s_alpha[16], s_beta[16], s_gamma[16];
    __shared__ int    s_frozen[16];
    if (tid < 16) { s_beta[tid] = 0.f; s_gamma[tid] = 2.f; s_frozen[tid] = 0; }
    __syncthreads();

    unsigned gen = g_rel;   // stable from previous launch

    #pragma unroll 1
    for (int it = 0; it < CG_ITERS; ++it) {
        // ---- phase 1: p = r + beta*p_old (RMW, owner-only; no reg state) ----
        if (valid) {
            #pragma unroll
            for (int u = 0; u < 4; u++) {
                float4 po = g_p[base4+u];
                float4 rv = g_r[base4+u];
                float4 pv;
                pv.x = fmaf(s_beta[4*u+0], po.x, rv.x);
                pv.y = fmaf(s_beta[4*u+1], po.y, rv.y);
                pv.z = fmaf(s_beta[4*u+2], po.z, rv.z);
                pv.w = fmaf(s_beta[4*u+3], po.w, rv.w);
                g_p[base4+u] = pv;
            }
        }
        gsync(++gen);

        // ---- phase 2: q = A p ; write q ; block-partial p.q ----
        {
            float pp[16], qq[16];
            if (valid) {
                #pragma unroll
                for (int u = 0; u < 4; u++) {
                    float4 pv = g_p[base4+u];
                    pp[4*u+0] = pv.x; pp[4*u+1] = pv.y;
                    pp[4*u+2] = pv.z; pp[4*u+3] = pv.w;
                }
                #pragma unroll
                for (int s = 0; s < 16; s++) qq[s] = EPSD * pp[s];
                if (i < 64) NB(base4 + 4*2145, g_cx[(i*65 + j)*33 + k]);
                if (i > 0)  NB(base4 - 4*2145, g_cx[((i-1)*65 + j)*33 + k]);
                if (j < 64) NB(base4 + 4*33,   g_cy[(i*64 + j)*33 + k]);
                if (j > 0)  NB(base4 - 4*33,   g_cy[(i*64 + (j-1))*33 + k]);
                if (k < 32) NB(base4 + 4,      g_cz[(i*65 + j)*32 + k]);
                if (k > 0)  NB(base4 - 4,      g_cz[(i*65 + j)*32 + (k-1)]);
                #pragma unroll
                for (int u = 0; u < 4; u++)
                    g_q[base4+u] = make_float4(qq[4*u], qq[4*u+1], qq[4*u+2], qq[4*u+3]);
            } else {
                #pragma unroll
                for (int s = 0; s < 16; s++) { pp[s] = 0.f; qq[s] = 0.f; }
            }
            BLOCKRED(pp[s]*qq[s], g_pqpart + bid*16);
        }
        gsync(++gen);

        // ---- phase 3: alpha; r -= alpha q; x_rx += alpha p; partial r.r ----
        if (tid < 64) {
            int s = tid & 15, prt = tid >> 4;
            double acc = 0.0;
            for (int b = prt; b < NBLK; b += 4) acc += (double)g_pqpart[b*16 + s];
            s_dred[tid] = acc;
        }
        __syncthreads();
        if (tid < 16) {
            double pq = s_dred[tid] + s_dred[16+tid] + s_dred[32+tid] + s_dred[48+tid];
            s_alpha[tid] = s_frozen[tid] ? 0.f : s_gamma[tid] / (float)pq;
        }
        __syncthreads();
        {
            float rr2[16];
            if (valid) {
                #pragma unroll
                for (int u = 0; u < 4; u++) {
                    float4 rv = g_r[base4+u];
                    float4 qv = g_q[base4+u];
                    rv.x = fmaf(-s_alpha[4*u+0], qv.x, rv.x);
                    rv.y = fmaf(-s_alpha[4*u+1], qv.y, rv.y);
                    rv.z = fmaf(-s_alpha[4*u+2], qv.z, rv.z);
                    rv.w = fmaf(-s_alpha[4*u+3], qv.w, rv.w);
                    g_r[base4+u] = rv;
                    rr2[4*u+0] = rv.x; rr2[4*u+1] = rv.y;
                    rr2[4*u+2] = rv.z; rr2[4*u+3] = rv.w;
                }
                if (slot >= 0) {
                    #pragma unroll
                    for (int u = 0; u < 4; u++) {
                        float4 pv = g_p[base4+u];
                        g_xsel[slot*16 + 4*u+0] += s_alpha[4*u+0] * pv.x;
                        g_xsel[slot*16 + 4*u+1] += s_alpha[4*u+1] * pv.y;
                        g_xsel[slot*16 + 4*u+2] += s_alpha[4*u+2] * pv.z;
                        g_xsel[slot*16 + 4*u+3] += s_alpha[4*u+3] * pv.w;
                    }
                }
            } else {
                #pragma unroll
                for (int s = 0; s < 16; s++) rr2[s] = 0.f;
            }
            BLOCKRED(rr2[s]*rr2[s], g_g2part + bid*16);
        }
        gsync(++gen);

        // ---- tail: gamma_new, beta, frozen (block-local, deterministic) ----
        if (tid < 64) {
            int s = tid & 15, prt = tid >> 4;
            double acc = 0.0;
            for (int b = prt; b < NBLK; b += 4) acc += (double)g_g2part[b*16 + s];
            s_dred[tid] = acc;
        }
        __syncthreads();
        if (tid < 16) {
            double gn = s_dred[tid] + s_dred[16+tid] + s_dred[32+tid] + s_dred[48+tid];
            float gnf = (float)gn;
            float b = s_frozen[tid] ? 0.f : gnf / s_gamma[tid];
            s_gamma[tid] = gnf;
            if (gn <= ATOL2) s_frozen[tid] = 1;
            s_beta[tid] = b;
        }
        __syncthreads();
    }
}

// ---------------- loss ----------------
__global__ void k_loss(const float* __restrict__ infm, const float* __restrict__ start,
                       const float* __restrict__ ref, float* __restrict__ out) {
    __shared__ double sd[256];
    __shared__ double sm[256];
    int t = threadIdx.x;
    int s = t >> 4;                   // source index
    int r = t & 15;                   // receiver index
    float d = g_xsel[r*16 + s] - g_xsel[(16+r)*16 + s];
    float diff = d - ref[t];
    sd[t] = (double)diff * (double)diff;
    double lm = 0.0;
    for (int idx = t; idx < NACT; idx += 256) {
        float dd = infm[idx] - start[idx];
        lm += (double)dd * (double)dd;
    }
    sm[t] = lm;
    __syncthreads();
    for (int off = 128; off >= 1; off >>= 1) {
        if (t < off) { sd[t] += sd[t+off]; sm[t] += sm[t+off]; }
        __syncthreads();
    }
    if (t == 0) {
        float loss_data  = (float)(sd[0] / 256.0);
        float loss_model = (float)(sm[0] / (double)NACT);
        out[0] = loss_data;           // alpha = 0.0 -> total == loss_data
        out[1] = loss_data;
        out[2] = loss_model;
    }
}

// zero-fill p/r/xsel only (separate from setb to avoid write races)
__global__ void k_zero() {
    int t = blockIdx.x*blockDim.x + threadIdx.x;
    if (t < NNODES*4) {
        float4 z = make_float4(0.f,0.f,0.f,0.f);
        g_p[t] = z; g_r[t] = z;
    }
    if (t < 32*16) g_xsel[t] = 0.f;
}

// ---------------- launch ----------------
extern "C" void kernel_launch(void* const* d_in, const int* in_sizes, int n_in,
                              void* d_out, int out_size) {
    const float* infm  = (const float*)d_in[0];
    const float* start = (const float*)d_in[1];
    const float* dref  = (const float*)d_in[2];
    const int*   act   = (const int*)  d_in[3];
    const int*   sa    = (const int*)  d_in[4];
    const int*   sb    = (const int*)  d_in[5];
    const int*   rxm   = (const int*)  d_in[6];
    const int*   rxn   = (const int*)  d_in[7];
    float* out = (float*)d_out;

    k_init_sigma<<<(NCELLS+255)/256, 256>>>();
    k_scatter<<<(NACT+255)/256, 256>>>(act, infm);
    k_coeffs<<<(NCX+NCY+NCZ+255)/256, 256>>>();
    k_zero<<<(NNODES*4+255)/256, 256>>>();
    k_setb<<<1, 32>>>(sa, sb);
    k_persist<<<NBLK, NTHR>>>(rxm, rxn);
    k_loss<<<1, 256>>>(infm, start, dref, out);
}

// round 5
// speedup vs baseline: 1.2209x; 1.2209x over previous
#include <cuda_runtime.h>

// ---------------- problem constants ----------------
#define NNODES 139425          // 65*65*33
#define NCELLS 131072          // 64*64*32
#define NACT   81920
#define EPSD   1.0e-7f
#define ATOL2  2.0e-12         // (1e-6)^2 * ||b||^2, ||b||^2 = 2
#define NCX 137280             // 64*65*33
#define NCY 137280             // 65*64*33
#define NCZ 135200             // 65*65*32
#define CG_ITERS 100
#define NBLK 148
#define NTHR 1024

// ---------------- device scratch ----------------
__device__ float4 g_p[NNODES*4];
__device__ float  g_sigma[NCELLS];
__device__ float  g_cx[NCX];
__device__ float  g_cy[NCY];
__device__ float  g_cz[NCZ];
__device__ float  g_pqpart[NBLK*16];
__device__ float  g_g2part[NBLK*16];
__device__ float  g_xsel[32*16];
__device__ volatile unsigned g_arr[NBLK];
__device__ volatile unsigned g_rel;

// ---------------- setup kernels ----------------
__global__ void k_init_sigma() {
    int t = blockIdx.x*blockDim.x + threadIdx.x;
    if (t < NCELLS) g_sigma[t] = 1.0e-8f;            // 1/AIR_RES
}

__global__ void k_scatter(const int* __restrict__ act, const float* __restrict__ model) {
    int t = blockIdx.x*blockDim.x + threadIdx.x;
    if (t < NACT) g_sigma[act[t]] = 1.0f / model[t];
}

__global__ void k_coeffs() {
    int t = blockIdx.x*blockDim.x + threadIdx.x;
    if (t < NCX) {
        int k = t % 33; int r = t / 33; int j = r % 65; int i = r / 65;
        float s = 0.f;
        for (int jj = j-1; jj <= j; ++jj)
            for (int kk = k-1; kk <= k; ++kk)
                if (jj >= 0 && jj < 64 && kk >= 0 && kk < 32)
                    s += g_sigma[(i*64 + jj)*32 + kk];
        g_cx[t] = 6.25f * s;                          // 0.25 * 25.0
    } else if (t < NCX + NCY) {
        int e = t - NCX;
        int k = e % 33; int r = e / 33; int j = r % 64; int i = r / 64;
        float s = 0.f;
        for (int ii = i-1; ii <= i; ++ii)
            for (int kk = k-1; kk <= k; ++kk)
                if (ii >= 0 && ii < 64 && kk >= 0 && kk < 32)
                    s += g_sigma[(ii*64 + j)*32 + kk];
        g_cy[e] = 6.25f * s;
    } else if (t < NCX + NCY + NCZ) {
        int e = t - NCX - NCY;
        int k = e % 32; int r = e / 32; int j = r % 65; int i = r / 65;
        float s = 0.f;
        for (int ii = i-1; ii <= i; ++ii)
            for (int jj = j-1; jj <= j; ++jj)
                if (ii >= 0 && ii < 64 && jj >= 0 && jj < 64)
                    s += g_sigma[(ii*64 + jj)*32 + k];
        g_cz[e] = 6.25f * s;
    }
}

// zero p and x-slots
__global__ void k_zero() {
    int t = blockIdx.x*blockDim.x + threadIdx.x;
    if (t < NNODES*4) g_p[t] = make_float4(0.f,0.f,0.f,0.f);
    if (t < 32*16) g_xsel[t] = 0.f;
}

// ---------------- software grid barrier ----------------
__device__ __forceinline__ void gsync(unsigned target) {
    __syncthreads();
    if (threadIdx.x == 0) {
        __threadfence();
        g_arr[blockIdx.x] = target;
    }
    if (blockIdx.x == 0) {
        if (threadIdx.x < 32) {
            for (int b = (int)threadIdx.x; b < NBLK; b += 32) {
                while (g_arr[b] < target) { }
            }
            __syncwarp();
            if (threadIdx.x == 0) { __threadfence(); g_rel = target; }
        }
    } else {
        if (threadIdx.x == 0) {
            while (g_rel < target) { }
            __threadfence();
        }
    }
    __syncthreads();
}

// warp-shuffle reduce 4 floats (one quad) -> s_red[wid*16 + 4u + c]
#define QUADRED(v0, v1, v2, v3, u)                                             \
    {                                                                          \
        float a0=(v0), a1=(v1), a2=(v2), a3=(v3);                              \
        a0 += __shfl_down_sync(0xffffffffu, a0, 16);                           \
        a1 += __shfl_down_sync(0xffffffffu, a1, 16);                           \
        a2 += __shfl_down_sync(0xffffffffu, a2, 16);                           \
        a3 += __shfl_down_sync(0xffffffffu, a3, 16);                           \
        a0 += __shfl_down_sync(0xffffffffu, a0, 8);                            \
        a1 += __shfl_down_sync(0xffffffffu, a1, 8);                            \
        a2 += __shfl_down_sync(0xffffffffu, a2, 8);                            \
        a3 += __shfl_down_sync(0xffffffffu, a3, 8);                            \
        a0 += __shfl_down_sync(0xffffffffu, a0, 4);                            \
        a1 += __shfl_down_sync(0xffffffffu, a1, 4);                            \
        a2 += __shfl_down_sync(0xffffffffu, a2, 4);                            \
        a3 += __shfl_down_sync(0xffffffffu, a3, 4);                            \
        a0 += __shfl_down_sync(0xffffffffu, a0, 2);                            \
        a1 += __shfl_down_sync(0xffffffffu, a1, 2);                            \
        a2 += __shfl_down_sync(0xffffffffu, a2, 2);                            \
        a3 += __shfl_down_sync(0xffffffffu, a3, 2);                            \
        a0 += __shfl_down_sync(0xffffffffu, a0, 1);                            \
        a1 += __shfl_down_sync(0xffffffffu, a1, 1);                            \
        a2 += __shfl_down_sync(0xffffffffu, a2, 1);                            \
        a3 += __shfl_down_sync(0xffffffffu, a3, 1);                            \
        if (lane == 0) {                                                       \
            s_red[wid*16 + 4*(u) + 0] = a0;                                    \
            s_red[wid*16 + 4*(u) + 1] = a1;                                    \
            s_red[wid*16 + 4*(u) + 2] = a2;                                    \
            s_red[wid*16 + 4*(u) + 3] = a3;                                    \
        }                                                                      \
    }

// cross-warp finish: sum s_red over 32 warps -> gout[0..15]
#define CROSSRED(gout)                                                         \
    {                                                                          \
        __syncthreads();                                                       \
        if (tid < 16) {                                                        \
            float acc = 0.f;                                                   \
            _Pragma("unroll")                                                  \
            for (int w = 0; w < 32; w++) acc += s_red[w*16 + tid];             \
            s_cross[tid] = acc;                                                \
        }                                                                      \
        __syncthreads();                                                       \
        if (tid == 0) {                                                        \
            float4* o = (float4*)(gout);                                       \
            const float4* c = (const float4*)s_cross;                          \
            o[0] = c[0]; o[1] = c[1]; o[2] = c[2]; o[3] = c[3];                \
        }                                                                      \
    }

// ---------------- persistent CG kernel ----------------
__global__ void __launch_bounds__(NTHR, 1)
k_persist(const int* __restrict__ sa, const int* __restrict__ sb,
          const int* __restrict__ rxm, const int* __restrict__ rxn)
{
    const int tid = threadIdx.x;
    const int bid = blockIdx.x;
    const int lane = tid & 31;
    const int wid  = tid >> 5;
    const int node = bid*NTHR + tid;
    const bool valid = node < NNODES;

    int base4 = 0;
    float cxp=0.f, cxm=0.f, cyp=0.f, cym=0.f, czp=0.f, czm=0.f;
    if (valid) {
        int k = node % 33;
        int ij = node / 33;
        int j = ij % 65;
        int i = ij / 65;
        base4 = node * 4;
        // iteration-invariant stencil coefficients, 0 on boundary
        if (i < 64) cxp = g_cx[(i*65 + j)*33 + k];
        if (i > 0)  cxm = g_cx[((i-1)*65 + j)*33 + k];
        if (j < 64) cyp = g_cy[(i*64 + j)*33 + k];
        if (j > 0)  cym = g_cy[(i*64 + (j-1))*33 + k];
        if (k < 32) czp = g_cz[(i*65 + j)*32 + k];
        if (k > 0)  czm = g_cz[(i*65 + j)*32 + (k-1)];
    }

    // receiver-slot ownership (32 distinct nodes)
    int slot = -1;
    if (valid) {
        for (int r2 = 0; r2 < 16; r2++) {
            if (node == rxm[r2]) slot = r2;
            if (node == rxn[r2]) slot = 16 + r2;
        }
    }

    // r = b in registers; persists for whole kernel
    float rr[16];
    #pragma unroll
    for (int s = 0; s < 16; s++) rr[s] = 0.f;
    if (valid) {
        #pragma unroll
        for (int s = 0; s < 16; s++) {
            if (node == sa[s]) rr[s] += 1.f;
            if (node == sb[s]) rr[s] -= 1.f;
        }
    }

    __shared__ float  s_red[32*16];
    __shared__ float  s_cross[16];
    __shared__ double s_dred[64];
    __shared__ float  s_alpha[16], s_beta[16], s_gamma[16];
    __shared__ int    s_frozen[16];
    if (tid < 16) { s_beta[tid] = 0.f; s_gamma[tid] = 2.f; s_frozen[tid] = 0; }
    __syncthreads();

    unsigned gen = g_rel;

    float qq[16];          // persists P2 -> P3 only
    #pragma unroll
    for (int s = 0; s < 16; s++) qq[s] = 0.f;

    #pragma unroll 1
    for (int it = 0; it < CG_ITERS; ++it) {
        // ---- phase 1: p = r + beta * p_old (RMW own p; r in regs) ----
        if (valid) {
            #pragma unroll
            for (int u = 0; u < 4; u++) {
                float4 po = g_p[base4+u];
                float4 pv;
                pv.x = fmaf(s_beta[4*u+0], po.x, rr[4*u+0]);
                pv.y = fmaf(s_beta[4*u+1], po.y, rr[4*u+1]);
                pv.z = fmaf(s_beta[4*u+2], po.z, rr[4*u+2]);
                pv.w = fmaf(s_beta[4*u+3], po.w, rr[4*u+3]);
                g_p[base4+u] = pv;
            }
        }
        gsync(++gen);

        // ---- phase 2: q = A p ; per-quad p.q reduction ----
        #pragma unroll
        for (int u = 0; u < 4; u++) {
            float q0=0.f, q1=0.f, q2=0.f, q3=0.f;
            float p0=0.f, p1=0.f, p2=0.f, p3=0.f;
            if (valid) {
                float4 pv = g_p[base4+u];
                p0 = pv.x; p1 = pv.y; p2 = pv.z; p3 = pv.w;
                q0 = EPSD*p0; q1 = EPSD*p1; q2 = EPSD*p2; q3 = EPSD*p3;
                if (cxp != 0.f) {
                    float4 pn = g_p[base4 + 4*2145 + u];
                    q0 += cxp*(p0-pn.x); q1 += cxp*(p1-pn.y);
                    q2 += cxp*(p2-pn.z); q3 += cxp*(p3-pn.w);
                }
                if (cxm != 0.f) {
                    float4 pn = g_p[base4 - 4*2145 + u];
                    q0 += cxm*(p0-pn.x); q1 += cxm*(p1-pn.y);
                    q2 += cxm*(p2-pn.z); q3 += cxm*(p3-pn.w);
                }
                if (cyp != 0.f) {
                    float4 pn = g_p[base4 + 4*33 + u];
                    q0 += cyp*(p0-pn.x); q1 += cyp*(p1-pn.y);
                    q2 += cyp*(p2-pn.z); q3 += cyp*(p3-pn.w);
                }
                if (cym != 0.f) {
                    float4 pn = g_p[base4 - 4*33 + u];
                    q0 += cym*(p0-pn.x); q1 += cym*(p1-pn.y);
                    q2 += cym*(p2-pn.z); q3 += cym*(p3-pn.w);
                }
                if (czp != 0.f) {
                    float4 pn = g_p[base4 + 4 + u];
                    q0 += czp*(p0-pn.x); q1 += czp*(p1-pn.y);
                    q2 += czp*(p2-pn.z); q3 += czp*(p3-pn.w);
                }
                if (czm != 0.f) {
                    float4 pn = g_p[base4 - 4 + u];
                    q0 += czm*(p0-pn.x); q1 += czm*(p1-pn.y);
                    q2 += czm*(p2-pn.z); q3 += czm*(p3-pn.w);
                }
            }
            qq[4*u+0]=q0; qq[4*u+1]=q1; qq[4*u+2]=q2; qq[4*u+3]=q3;
            QUADRED(p0*q0, p1*q1, p2*q2, p3*q3, u);
        }
        CROSSRED(g_pqpart + bid*16);
        gsync(++gen);

        // ---- phase 3: alpha; r -= alpha q (regs); x_rx += alpha p; r.r ----
        if (tid < 64) {
            int s = tid & 15, prt = tid >> 4;
            double acc = 0.0;
            for (int b = prt; b < NBLK; b += 4) acc += (double)g_pqpart[b*16 + s];
            s_dred[tid] = acc;
        }
        __syncthreads();
        if (tid < 16) {
            double pq = s_dred[tid] + s_dred[16+tid] + s_dred[32+tid] + s_dred[48+tid];
            s_alpha[tid] = s_frozen[tid] ? 0.f : s_gamma[tid] / (float)pq;
        }
        __syncthreads();
        if (valid) {
            #pragma unroll
            for (int s = 0; s < 16; s++) rr[s] = fmaf(-s_alpha[s], qq[s], rr[s]);
            if (slot >= 0) {
                #pragma unroll
                for (int u = 0; u < 4; u++) {
                    float4 pv = g_p[base4+u];
                    g_xsel[slot*16 + 4*u+0] += s_alpha[4*u+0] * pv.x;
                    g_xsel[slot*16 + 4*u+1] += s_alpha[4*u+1] * pv.y;
                    g_xsel[slot*16 + 4*u+2] += s_alpha[4*u+2] * pv.z;
                    g_xsel[slot*16 + 4*u+3] += s_alpha[4*u+3] * pv.w;
                }
            }
        }
        #pragma unroll
        for (int u = 0; u < 4; u++)
            QUADRED(rr[4*u]*rr[4*u], rr[4*u+1]*rr[4*u+1],
                    rr[4*u+2]*rr[4*u+2], rr[4*u+3]*rr[4*u+3], u);
        CROSSRED(g_g2part + bid*16);
        gsync(++gen);

        // ---- tail: gamma_new, beta, frozen (block-local, deterministic) ----
        if (tid < 64) {
            int s = tid & 15, prt = tid >> 4;
            double acc = 0.0;
            for (int b = prt; b < NBLK; b += 4) acc += (double)g_g2part[b*16 + s];
            s_dred[tid] = acc;
        }
        __syncthreads();
        if (tid < 16) {
            double gn = s_dred[tid] + s_dred[16+tid] + s_dred[32+tid] + s_dred[48+tid];
            float gnf = (float)gn;
            float b = s_frozen[tid] ? 0.f : gnf / s_gamma[tid];
            s_gamma[tid] = gnf;
            if (gn <= ATOL2) s_frozen[tid] = 1;
            s_beta[tid] = b;
        }
        __syncthreads();
    }
}

// ---------------- loss ----------------
__global__ void k_loss(const float* __restrict__ infm, const float* __restrict__ start,
                       const float* __restrict__ ref, float* __restrict__ out) {
    __shared__ double sd[256];
    __shared__ double sm[256];
    int t = threadIdx.x;
    int s = t >> 4;                   // source index
    int r = t & 15;                   // receiver index
    float d = g_xsel[r*16 + s] - g_xsel[(16+r)*16 + s];
    float diff = d - ref[t];
    sd[t] = (double)diff * (double)diff;
    double lm = 0.0;
    for (int idx = t; idx < NACT; idx += 256) {
        float dd = infm[idx] - start[idx];
        lm += (double)dd * (double)dd;
    }
    sm[t] = lm;
    __syncthreads();
    for (int off = 128; off >= 1; off >>= 1) {
        if (t < off) { sd[t] += sd[t+off]; sm[t] += sm[t+off]; }
        __syncthreads();
    }
    if (t == 0) {
        float loss_data  = (float)(sd[0] / 256.0);
        float loss_model = (float)(sm[0] / (double)NACT);
        out[0] = loss_data;           // alpha = 0.0 -> total == loss_data
        out[1] = loss_data;
        out[2] = loss_model;
    }
}

// ---------------- launch ----------------
extern "C" void kernel_launch(void* const* d_in, const int* in_sizes, int n_in,
                              void* d_out, int out_size) {
    const float* infm  = (const float*)d_in[0];
    const float* start = (const float*)d_in[1];
    const float* dref  = (const float*)d_in[2];
    const int*   act   = (const int*)  d_in[3];
    const int*   sa    = (const int*)  d_in[4];
    const int*   sb    = (const int*)  d_in[5];
    const int*   rxm   = (const int*)  d_in[6];
    const int*   rxn   = (const int*)  d_in[7];
    float* out = (float*)d_out;

    k_init_sigma<<<(NCELLS+255)/256, 256>>>();
    k_scatter<<<(NACT+255)/256, 256>>>(act, infm);
    k_coeffs<<<(NCX+NCY+NCZ+255)/256, 256>>>();
    k_zero<<<(NNODES*4+255)/256, 256>>>();
    k_persist<<<NBLK, NTHR>>>(sa, sb, rxm, rxn);
    k_loss<<<1, 256>>>(infm, start, dref, out);
}

// round 6
// speedup vs baseline: 1.4766x; 1.2095x over previous
#include <cuda_runtime.h>

// ---------------- problem constants ----------------
#define NNODES 139425          // 65*65*33
#define NCELLS 131072          // 64*64*32
#define NACT   81920
#define EPSD   1.0e-7f
#define ATOL2  2.0e-12         // (1e-6)^2 * ||b||^2, ||b||^2 = 2
#define NCX 137280             // 64*65*33
#define NCY 137280             // 65*64*33
#define NCZ 135200             // 65*65*32
#define CG_ITERS 100
#define NBLK 148
#define NTHR 1024
#define DSMEM (2*4*1024*16)    // p-tile + r-tile, float4: 131072 B

// ---------------- device scratch ----------------
__device__ float4 g_p[NNODES*4];
__device__ float  g_sigma[NCELLS];
__device__ float  g_cx[NCX];
__device__ float  g_cy[NCY];
__device__ float  g_cz[NCZ];
__device__ float  g_pqpart[NBLK*16];
__device__ float  g_g2part[NBLK*16];
__device__ float  g_xsel[32*16];
__device__ volatile unsigned g_arr[NBLK];
__device__ volatile unsigned g_rel;

// ---------------- setup kernels ----------------
__global__ void k_init_sigma() {
    int t = blockIdx.x*blockDim.x + threadIdx.x;
    if (t < NCELLS) g_sigma[t] = 1.0e-8f;            // 1/AIR_RES
}

__global__ void k_scatter(const int* __restrict__ act, const float* __restrict__ model) {
    int t = blockIdx.x*blockDim.x + threadIdx.x;
    if (t < NACT) g_sigma[act[t]] = 1.0f / model[t];
}

__global__ void k_coeffs() {
    int t = blockIdx.x*blockDim.x + threadIdx.x;
    if (t < NCX) {
        int k = t % 33; int r = t / 33; int j = r % 65; int i = r / 65;
        float s = 0.f;
        for (int jj = j-1; jj <= j; ++jj)
            for (int kk = k-1; kk <= k; ++kk)
                if (jj >= 0 && jj < 64 && kk >= 0 && kk < 32)
                    s += g_sigma[(i*64 + jj)*32 + kk];
        g_cx[t] = 6.25f * s;                          // 0.25 * 25.0
    } else if (t < NCX + NCY) {
        int e = t - NCX;
        int k = e % 33; int r = e / 33; int j = r % 64; int i = r / 64;
        float s = 0.f;
        for (int ii = i-1; ii <= i; ++ii)
            for (int kk = k-1; kk <= k; ++kk)
                if (ii >= 0 && ii < 64 && kk >= 0 && kk < 32)
                    s += g_sigma[(ii*64 + j)*32 + kk];
        g_cy[e] = 6.25f * s;
    } else if (t < NCX + NCY + NCZ) {
        int e = t - NCX - NCY;
        int k = e % 32; int r = e / 32; int j = r % 65; int i = r / 65;
        float s = 0.f;
        for (int ii = i-1; ii <= i; ++ii)
            for (int jj = j-1; jj <= j; ++jj)
                if (ii >= 0 && ii < 64 && jj >= 0 && jj < 64)
                    s += g_sigma[(ii*64 + jj)*32 + k];
        g_cz[e] = 6.25f * s;
    }
}

// ---------------- software grid barrier ----------------
__device__ __forceinline__ void gsync(unsigned target) {
    __syncthreads();
    if (threadIdx.x == 0) {
        __threadfence();
        g_arr[blockIdx.x] = target;
    }
    if (blockIdx.x == 0) {
        if (threadIdx.x < 32) {
            for (int b = (int)threadIdx.x; b < NBLK; b += 32) {
                while (g_arr[b] < target) { }
            }
            __syncwarp();
            if (threadIdx.x == 0) { __threadfence(); g_rel = target; }
        }
    } else {
        if (threadIdx.x == 0) {
            while (g_rel < target) { }
            __threadfence();
        }
    }
    __syncthreads();
}

// warp-shuffle reduce 4 floats (one quad) -> s_red[wid*16 + 4u + c]
#define QUADRED(v0, v1, v2, v3, u)                                             \
    {                                                                          \
        float a0=(v0), a1=(v1), a2=(v2), a3=(v3);                              \
        a0 += __shfl_down_sync(0xffffffffu, a0, 16);                           \
        a1 += __shfl_down_sync(0xffffffffu, a1, 16);                           \
        a2 += __shfl_down_sync(0xffffffffu, a2, 16);                           \
        a3 += __shfl_down_sync(0xffffffffu, a3, 16);                           \
        a0 += __shfl_down_sync(0xffffffffu, a0, 8);                            \
        a1 += __shfl_down_sync(0xffffffffu, a1, 8);                            \
        a2 += __shfl_down_sync(0xffffffffu, a2, 8);                            \
        a3 += __shfl_down_sync(0xffffffffu, a3, 8);                            \
        a0 += __shfl_down_sync(0xffffffffu, a0, 4);                            \
        a1 += __shfl_down_sync(0xffffffffu, a1, 4);                            \
        a2 += __shfl_down_sync(0xffffffffu, a2, 4);                            \
        a3 += __shfl_down_sync(0xffffffffu, a3, 4);                            \
        a0 += __shfl_down_sync(0xffffffffu, a0, 2);                            \
        a1 += __shfl_down_sync(0xffffffffu, a1, 2);                            \
        a2 += __shfl_down_sync(0xffffffffu, a2, 2);                            \
        a3 += __shfl_down_sync(0xffffffffu, a3, 2);                            \
        a0 += __shfl_down_sync(0xffffffffu, a0, 1);                            \
        a1 += __shfl_down_sync(0xffffffffu, a1, 1);                            \
        a2 += __shfl_down_sync(0xffffffffu, a2, 1);                            \
        a3 += __shfl_down_sync(0xffffffffu, a3, 1);                            \
        if (lane == 0) {                                                       \
            s_red[wid*16 + 4*(u) + 0] = a0;                                    \
            s_red[wid*16 + 4*(u) + 1] = a1;                                    \
            s_red[wid*16 + 4*(u) + 2] = a2;                                    \
            s_red[wid*16 + 4*(u) + 3] = a3;                                    \
        }                                                                      \
    }

// cross-warp finish: sum s_red over 32 warps -> gout[0..15]
#define CROSSRED(gout)                                                         \
    {                                                                          \
        __syncthreads();                                                       \
        if (tid < 16) {                                                        \
            float acc = 0.f;                                                   \
            _Pragma("unroll")                                                  \
            for (int w = 0; w < 32; w++) acc += s_red[w*16 + tid];             \
            s_cross[tid] = acc;                                                \
        }                                                                      \
        __syncthreads();                                                       \
        if (tid == 0) {                                                        \
            float4* o = (float4*)(gout);                                       \
            const float4* c = (const float4*)s_cross;                          \
            o[0] = c[0]; o[1] = c[1]; o[2] = c[2]; o[3] = c[3];                \
        }                                                                      \
    }

// accumulate one neighbor quad into q0..q3
#define ACC(pn)                                                                \
    {                                                                          \
        q0 = fmaf(c_, p0 - (pn).x, q0);                                        \
        q1 = fmaf(c_, p1 - (pn).y, q1);                                        \
        q2 = fmaf(c_, p2 - (pn).z, q2);                                        \
        q3 = fmaf(c_, p3 - (pn).w, q3);                                        \
    }

// ---------------- persistent CG kernel ----------------
__global__ void __launch_bounds__(NTHR, 1)
k_persist(const int* __restrict__ sa, const int* __restrict__ sb,
          const int* __restrict__ rxm, const int* __restrict__ rxn)
{
    extern __shared__ float4 s_dyn[];
    float4* s_p = s_dyn;               // [4][1024]  p tile, SoA by quad
    float4* s_r = s_dyn + 4096;        // [4][1024]  r tile

    const int tid = threadIdx.x;
    const int bid = blockIdx.x;
    const int lane = tid & 31;
    const int wid  = tid >> 5;
    const int node = bid*NTHR + tid;
    const bool valid = node < NNODES;

    int base4 = 0;
    float cxp=0.f, cxm=0.f, cyp=0.f, cym=0.f, czp=0.f, czm=0.f;
    if (valid) {
        int k = node % 33;
        int ij = node / 33;
        int j = ij % 65;
        int i = ij / 65;
        base4 = node * 4;
        if (i < 64) cxp = g_cx[(i*65 + j)*33 + k];
        if (i > 0)  cxm = g_cx[((i-1)*65 + j)*33 + k];
        if (j < 64) cyp = g_cy[(i*64 + j)*33 + k];
        if (j > 0)  cym = g_cy[(i*64 + (j-1))*33 + k];
        if (k < 32) czp = g_cz[(i*65 + j)*32 + k];
        if (k > 0)  czm = g_cz[(i*65 + j)*32 + (k-1)];
    }

    // receiver-slot ownership (32 distinct nodes); zero x accumulators
    int slot = -1;
    if (valid) {
        for (int r2 = 0; r2 < 16; r2++) {
            if (node == rxm[r2]) slot = r2;
            if (node == rxn[r2]) slot = 16 + r2;
        }
        if (slot >= 0) {
            float4* xs = (float4*)&g_xsel[slot*16];
            float4 z = make_float4(0.f,0.f,0.f,0.f);
            xs[0]=z; xs[1]=z; xs[2]=z; xs[3]=z;
        }
    }

    // init tiles: p = 0, r = b
    {
        float4 z = make_float4(0.f,0.f,0.f,0.f);
        #pragma unroll
        for (int u = 0; u < 4; u++) { s_p[u*1024+tid] = z; s_r[u*1024+tid] = z; }
        if (valid) {
            float* rf = (float*)s_r;
            #pragma unroll
            for (int s = 0; s < 16; s++) {
                float bv = 0.f;
                if (node == sa[s]) bv += 1.f;
                if (node == sb[s]) bv -= 1.f;
                if (bv != 0.f) rf[(s>>2)*4096 + tid*4 + (s&3)] = bv;
            }
        }
    }

    __shared__ float  s_red[32*16];
    __shared__ float  s_cross[16];
    __shared__ double s_dred[64];
    __shared__ float  s_alpha[16], s_beta[16], s_gamma[16];
    __shared__ int    s_frozen[16];
    if (tid < 16) { s_beta[tid] = 0.f; s_gamma[tid] = 2.f; s_frozen[tid] = 0; }
    __syncthreads();

    unsigned gen = g_rel;

    float qq[16];          // persists P2 -> P3 only
    #pragma unroll
    for (int s = 0; s < 16; s++) qq[s] = 0.f;

    #pragma unroll 1
    for (int it = 0; it < CG_ITERS; ++it) {
        // ---- phase 1: p = r + beta*p_old (tiles); publish p to global ----
        #pragma unroll
        for (int u = 0; u < 4; u++) {
            float4 po = s_p[u*1024+tid];
            float4 rv = s_r[u*1024+tid];
            float4 pv;
            pv.x = fmaf(s_beta[4*u+0], po.x, rv.x);
            pv.y = fmaf(s_beta[4*u+1], po.y, rv.y);
            pv.z = fmaf(s_beta[4*u+2], po.z, rv.z);
            pv.w = fmaf(s_beta[4*u+3], po.w, rv.w);
            s_p[u*1024+tid] = pv;
            if (valid) g_p[base4+u] = pv;
        }
        gsync(++gen);

        // ---- phase 2: q = A p (smem j/k, global i/halo); dot p.q ----
        #pragma unroll
        for (int u = 0; u < 4; u++) {
            float4 pv = s_p[u*1024+tid];
            float p0 = pv.x, p1 = pv.y, p2 = pv.z, p3 = pv.w;
            float q0 = EPSD*p0, q1 = EPSD*p1, q2 = EPSD*p2, q3 = EPSD*p3;
            if (cxp != 0.f) { float c_ = cxp; float4 pn = g_p[base4 + 8580 + u]; ACC(pn); }
            if (cxm != 0.f) { float c_ = cxm; float4 pn = g_p[base4 - 8580 + u]; ACC(pn); }
            if (cyp != 0.f) {
                float c_ = cyp;
                float4 pn = (tid + 33 < NTHR) ? s_p[u*1024+tid+33] : g_p[base4 + 132 + u];
                ACC(pn);
            }
            if (cym != 0.f) {
                float c_ = cym;
                float4 pn = (tid >= 33) ? s_p[u*1024+tid-33] : g_p[base4 - 132 + u];
                ACC(pn);
            }
            if (czp != 0.f) {
                float c_ = czp;
                float4 pn = (tid + 1 < NTHR) ? s_p[u*1024+tid+1] : g_p[base4 + 4 + u];
                ACC(pn);
            }
            if (czm != 0.f) {
                float c_ = czm;
                float4 pn = (tid >= 1) ? s_p[u*1024+tid-1] : g_p[base4 - 4 + u];
                ACC(pn);
            }
            qq[4*u+0]=q0; qq[4*u+1]=q1; qq[4*u+2]=q2; qq[4*u+3]=q3;
            QUADRED(p0*q0, p1*q1, p2*q2, p3*q3, u);
        }
        CROSSRED(g_pqpart + bid*16);
        gsync(++gen);

        // ---- phase 3: alpha (redundant per block); r -= alpha q; x; r.r ----
        if (tid < 64) {
            int s = tid & 15, prt = tid >> 4;
            double acc = 0.0;
            for (int b = prt; b < NBLK; b += 4) acc += (double)g_pqpart[b*16 + s];
            s_dred[tid] = acc;
        }
        __syncthreads();
        if (tid < 16) {
            double pq = s_dred[tid] + s_dred[16+tid] + s_dred[32+tid] + s_dred[48+tid];
            s_alpha[tid] = s_frozen[tid] ? 0.f : s_gamma[tid] / (float)pq;
        }
        __syncthreads();
        #pragma unroll
        for (int u = 0; u < 4; u++) {
            float4 rv = s_r[u*1024+tid];
            rv.x = fmaf(-s_alpha[4*u+0], qq[4*u+0], rv.x);
            rv.y = fmaf(-s_alpha[4*u+1], qq[4*u+1], rv.y);
            rv.z = fmaf(-s_alpha[4*u+2], qq[4*u+2], rv.z);
            rv.w = fmaf(-s_alpha[4*u+3], qq[4*u+3], rv.w);
            s_r[u*1024+tid] = rv;
            QUADRED(rv.x*rv.x, rv.y*rv.y, rv.z*rv.z, rv.w*rv.w, u);
        }
        if (slot >= 0) {
            #pragma unroll
            for (int u = 0; u < 4; u++) {
                float4 pv = s_p[u*1024+tid];
                g_xsel[slot*16 + 4*u+0] += s_alpha[4*u+0] * pv.x;
                g_xsel[slot*16 + 4*u+1] += s_alpha[4*u+1] * pv.y;
                g_xsel[slot*16 + 4*u+2] += s_alpha[4*u+2] * pv.z;
                g_xsel[slot*16 + 4*u+3] += s_alpha[4*u+3] * pv.w;
            }
        }
        CROSSRED(g_g2part + bid*16);
        gsync(++gen);

        // ---- tail: gamma_new, beta, frozen (redundant per block) ----
        if (tid < 64) {
            int s = tid & 15, prt = tid >> 4;
            double acc = 0.0;
            for (int b = prt; b < NBLK; b += 4) acc += (double)g_g2part[b*16 + s];
            s_dred[tid] = acc;
        }
        __syncthreads();
        if (tid < 16) {
            double gn = s_dred[tid] + s_dred[16+tid] + s_dred[32+tid] + s_dred[48+tid];
            float gnf = (float)gn;
            float b = s_frozen[tid] ? 0.f : gnf / s_gamma[tid];
            s_gamma[tid] = gnf;
            if (gn <= ATOL2) s_frozen[tid] = 1;
            s_beta[tid] = b;
        }
        __syncthreads();
    }
}

// ---------------- loss ----------------
__global__ void k_loss(const float* __restrict__ infm, const float* __restrict__ start,
                       const float* __restrict__ ref, float* __restrict__ out) {
    __shared__ double sd[256];
    __shared__ double sm[256];
    int t = threadIdx.x;
    int s = t >> 4;                   // source index
    int r = t & 15;                   // receiver index
    float d = g_xsel[r*16 + s] - g_xsel[(16+r)*16 + s];
    float diff = d - ref[t];
    sd[t] = (double)diff * (double)diff;
    double lm = 0.0;
    for (int idx = t; idx < NACT; idx += 256) {
        float dd = infm[idx] - start[idx];
        lm += (double)dd * (double)dd;
    }
    sm[t] = lm;
    __syncthreads();
    for (int off = 128; off >= 1; off >>= 1) {
        if (t < off) { sd[t] += sd[t+off]; sm[t] += sm[t+off]; }
        __syncthreads();
    }
    if (t == 0) {
        float loss_data  = (float)(sd[0] / 256.0);
        float loss_model = (float)(sm[0] / (double)NACT);
        out[0] = loss_data;           // alpha = 0.0 -> total == loss_data
        out[1] = loss_data;
        out[2] = loss_model;
    }
}

// ---------------- launch ----------------
extern "C" void kernel_launch(void* const* d_in, const int* in_sizes, int n_in,
                              void* d_out, int out_size) {
    const float* infm  = (const float*)d_in[0];
    const float* start = (const float*)d_in[1];
    const float* dref  = (const float*)d_in[2];
    const int*   act   = (const int*)  d_in[3];
    const int*   sa    = (const int*)  d_in[4];
    const int*   sb    = (const int*)  d_in[5];
    const int*   rxm   = (const int*)  d_in[6];
    const int*   rxn   = (const int*)  d_in[7];
    float* out = (float*)d_out;

    static int attr_done = 0;
    if (!attr_done) {
        cudaFuncSetAttribute(k_persist, cudaFuncAttributeMaxDynamicSharedMemorySize, DSMEM);
        attr_done = 1;
    }

    k_init_sigma<<<(NCELLS+255)/256, 256>>>();
    k_scatter<<<(NACT+255)/256, 256>>>(act, infm);
    k_coeffs<<<(NCX+NCY+NCZ+255)/256, 256>>>();
    k_persist<<<NBLK, NTHR, DSMEM>>>(sa, sb, rxm, rxn);
    k_loss<<<1, 256>>>(infm, start, dref, out);
}

// round 7
// speedup vs baseline: 1.7812x; 1.2063x over previous
#include <cuda_runtime.h>

// ---------------- problem constants ----------------
#define NNODES 139425          // 65*65*33
#define NCELLS 131072          // 64*64*32
#define NACT   81920
#define EPSD   1.0e-7f
#define ATOL2  2.0e-12         // (1e-6)^2 * ||b||^2, ||b||^2 = 2
#define NCX 137280
#define NCY 137280
#define NCZ 135200
#define CG_ITERS 100
#define NBLK 148
#define NTHR 1024
#define DSMEM (3*4*1024*16)    // p, r, q tiles (float4): 196608 B

// ---------------- device scratch ----------------
__device__ float4 g_p[NNODES*4];
__device__ float  g_sigma[NCELLS];
__device__ float  g_cx[NCX];
__device__ float  g_cy[NCY];
__device__ float  g_cz[NCZ];
__device__ float  g_pqpart[NBLK*16];
__device__ float  g_g2part[NBLK*16];
__device__ float  g_xsel[32*16];
__device__ float  g_ab[32];            // alpha[0..15], beta[16..31]
__device__ float  g_gam[16];
__device__ int    g_froz[16];
__device__ unsigned g_cnt;
__device__ volatile unsigned g_rel2;

// ---------------- setup kernels ----------------
__global__ void k_init_sigma() {
    int t = blockIdx.x*blockDim.x + threadIdx.x;
    if (t < NCELLS) g_sigma[t] = 1.0e-8f;            // 1/AIR_RES
}

__global__ void k_scatter(const int* __restrict__ act, const float* __restrict__ model) {
    int t = blockIdx.x*blockDim.x + threadIdx.x;
    if (t < NACT) g_sigma[act[t]] = 1.0f / model[t];
}

__global__ void k_coeffs() {
    int t = blockIdx.x*blockDim.x + threadIdx.x;
    if (t < NCX) {
        int k = t % 33; int r = t / 33; int j = r % 65; int i = r / 65;
        float s = 0.f;
        for (int jj = j-1; jj <= j; ++jj)
            for (int kk = k-1; kk <= k; ++kk)
                if (jj >= 0 && jj < 64 && kk >= 0 && kk < 32)
                    s += g_sigma[(i*64 + jj)*32 + kk];
        g_cx[t] = 6.25f * s;                          // 0.25 * 25.0
    } else if (t < NCX + NCY) {
        int e = t - NCX;
        int k = e % 33; int r = e / 33; int j = r % 64; int i = r / 64;
        float s = 0.f;
        for (int ii = i-1; ii <= i; ++ii)
            for (int kk = k-1; kk <= k; ++kk)
                if (ii >= 0 && ii < 64 && kk >= 0 && kk < 32)
                    s += g_sigma[(ii*64 + j)*32 + kk];
        g_cy[e] = 6.25f * s;
    } else if (t < NCX + NCY + NCZ) {
        int e = t - NCX - NCY;
        int k = e % 32; int r = e / 32; int j = r % 65; int i = r / 65;
        float s = 0.f;
        for (int ii = i-1; ii <= i; ++ii)
            for (int jj = j-1; jj <= j; ++jj)
                if (ii >= 0 && ii < 64 && jj >= 0 && jj < 64)
                    s += g_sigma[(ii*64 + jj)*32 + k];
        g_cz[e] = 6.25f * s;
    }
}

// per-launch state reset (runs on every graph replay)
__global__ void k_zero() {
    int t = blockIdx.x*blockDim.x + threadIdx.x;
    if (t < NNODES*4) g_p[t] = make_float4(0.f,0.f,0.f,0.f);
    if (t < 32*16) g_xsel[t] = 0.f;
    if (t < 32) g_ab[t] = 0.f;
    if (t < 16) { g_gam[t] = 2.f; g_froz[t] = 0; }
}

// warp-shuffle reduce 4 floats (one quad) -> s_red[wid*16 + 4u + c]
#define QUADRED(v0, v1, v2, v3, u)                                             \
    {                                                                          \
        float a0=(v0), a1=(v1), a2=(v2), a3=(v3);                              \
        a0 += __shfl_down_sync(0xffffffffu, a0, 16);                           \
        a1 += __shfl_down_sync(0xffffffffu, a1, 16);                           \
        a2 += __shfl_down_sync(0xffffffffu, a2, 16);                           \
        a3 += __shfl_down_sync(0xffffffffu, a3, 16);                           \
        a0 += __shfl_down_sync(0xffffffffu, a0, 8);                            \
        a1 += __shfl_down_sync(0xffffffffu, a1, 8);                            \
        a2 += __shfl_down_sync(0xffffffffu, a2, 8);                            \
        a3 += __shfl_down_sync(0xffffffffu, a3, 8);                            \
        a0 += __shfl_down_sync(0xffffffffu, a0, 4);                            \
        a1 += __shfl_down_sync(0xffffffffu, a1, 4);                            \
        a2 += __shfl_down_sync(0xffffffffu, a2, 4);                            \
        a3 += __shfl_down_sync(0xffffffffu, a3, 4);                            \
        a0 += __shfl_down_sync(0xffffffffu, a0, 2);                            \
        a1 += __shfl_down_sync(0xffffffffu, a1, 2);                            \
        a2 += __shfl_down_sync(0xffffffffu, a2, 2);                            \
        a3 += __shfl_down_sync(0xffffffffu, a3, 2);                            \
        a0 += __shfl_down_sync(0xffffffffu, a0, 1);                            \
        a1 += __shfl_down_sync(0xffffffffu, a1, 1);                            \
        a2 += __shfl_down_sync(0xffffffffu, a2, 1);                            \
        a3 += __shfl_down_sync(0xffffffffu, a3, 1);                            \
        if (lane == 0) {                                                       \
            s_red[wid*16 + 4*(u) + 0] = a0;                                    \
            s_red[wid*16 + 4*(u) + 1] = a1;                                    \
            s_red[wid*16 + 4*(u) + 2] = a2;                                    \
            s_red[wid*16 + 4*(u) + 3] = a3;                                    \
        }                                                                      \
    }

// cross-warp finish: sum s_red over 32 warps -> gout[0..15]
#define CROSSRED(gout)                                                         \
    {                                                                          \
        __syncthreads();                                                       \
        if (tid < 16) {                                                        \
            float acc = 0.f;                                                   \
            _Pragma("unroll")                                                  \
            for (int w = 0; w < 32; w++) acc += s_red[w*16 + tid];             \
            s_cross[tid] = acc;                                                \
        }                                                                      \
        __syncthreads();                                                       \
        if (tid == 0) {                                                        \
            float4* o = (float4*)(gout);                                       \
            const float4* c = (const float4*)s_cross;                          \
            o[0] = c[0]; o[1] = c[1]; o[2] = c[2]; o[3] = c[3];                \
        }                                                                      \
    }

// barrier arrive: counter-based; sets s_last in the last-arriving block
#define BAR_ARRIVE()                                                           \
    gen++;                                                                     \
    __syncthreads();                                                           \
    if (tid == 0) {                                                            \
        __threadfence();                                                       \
        unsigned old = atomicAdd(&g_cnt, 1u);                                  \
        s_last = (old == gen*NBLK - 1u) ? 1 : 0;                               \
    }                                                                          \
    __syncthreads();

#define BAR_WAIT()                                                             \
    if (tid == 0) {                                                            \
        while (g_rel2 < gen) { }                                               \
        __threadfence();                                                       \
    }                                                                          \
    __syncthreads();

// accumulate one neighbor quad into q0..q3
#define ACC(pn)                                                                \
    {                                                                          \
        q0 = fmaf(c_, p0 - (pn).x, q0);                                        \
        q1 = fmaf(c_, p1 - (pn).y, q1);                                        \
        q2 = fmaf(c_, p2 - (pn).z, q2);                                        \
        q3 = fmaf(c_, p3 - (pn).w, q3);                                        \
    }

// ---------------- persistent CG kernel ----------------
__global__ void __launch_bounds__(NTHR, 1)
k_persist(const int* __restrict__ sa, const int* __restrict__ sb,
          const int* __restrict__ rxm, const int* __restrict__ rxn)
{
    extern __shared__ float4 s_dyn[];
    float4* s_p = s_dyn;               // [4][1024]
    float4* s_r = s_dyn + 4096;        // [4][1024]
    float4* s_q = s_dyn + 8192;        // [4][1024]

    const int tid = threadIdx.x;
    const int bid = blockIdx.x;
    const int lane = tid & 31;
    const int wid  = tid >> 5;
    const int node = bid*NTHR + tid;
    const bool valid = node < NNODES;

    int base4 = 0;
    float cxp=0.f, cxm=0.f, cyp=0.f, cym=0.f, czp=0.f, czm=0.f;
    if (valid) {
        int k = node % 33;
        int ij = node / 33;
        int j = ij % 65;
        int i = ij / 65;
        base4 = node * 4;
        if (i < 64) cxp = g_cx[(i*65 + j)*33 + k];
        if (i > 0)  cxm = g_cx[((i-1)*65 + j)*33 + k];
        if (j < 64) cyp = g_cy[(i*64 + j)*33 + k];
        if (j > 0)  cym = g_cy[(i*64 + (j-1))*33 + k];
        if (k < 32) czp = g_cz[(i*65 + j)*32 + k];
        if (k > 0)  czm = g_cz[(i*65 + j)*32 + (k-1)];
    }

    // receiver-slot ownership (32 distinct nodes)
    int slot = -1;
    if (valid) {
        for (int r2 = 0; r2 < 16; r2++) {
            if (node == rxm[r2]) slot = r2;
            if (node == rxn[r2]) slot = 16 + r2;
        }
    }

    // init tiles: p = 0, r = b
    {
        float4 z = make_float4(0.f,0.f,0.f,0.f);
        #pragma unroll
        for (int u = 0; u < 4; u++) { s_p[u*1024+tid] = z; s_r[u*1024+tid] = z; }
        if (valid) {
            float* rf = (float*)s_r;
            #pragma unroll
            for (int s = 0; s < 16; s++) {
                float bv = 0.f;
                if (node == sa[s]) bv += 1.f;
                if (node == sb[s]) bv -= 1.f;
                if (bv != 0.f) rf[(s>>2)*4096 + tid*4 + (s&3)] = bv;
            }
        }
    }

    __shared__ float  s_red[32*16];
    __shared__ float  s_cross[16];
    __shared__ double s_dred[128];
    __shared__ float  s_alpha[16], s_beta[16];
    __shared__ int    s_last;
    if (tid < 16) s_beta[tid] = 0.f;
    __syncthreads();

    unsigned gen = g_rel2;       // stable generation base from previous launch

    #pragma unroll 1
    for (int it = 0; it < CG_ITERS; ++it) {
        // ---- phase 1: p = r + beta*p_old (tiles); publish p to global ----
        #pragma unroll
        for (int u = 0; u < 4; u++) {
            float4 po = s_p[u*1024+tid];
            float4 rv = s_r[u*1024+tid];
            float4 pv;
            pv.x = fmaf(s_beta[4*u+0], po.x, rv.x);
            pv.y = fmaf(s_beta[4*u+1], po.y, rv.y);
            pv.z = fmaf(s_beta[4*u+2], po.z, rv.z);
            pv.w = fmaf(s_beta[4*u+3], po.w, rv.w);
            s_p[u*1024+tid] = pv;
            if (valid) g_p[base4+u] = pv;
        }
        // ---- barrier A (plain) ----
        BAR_ARRIVE();
        if (s_last) {
            if (tid == 0) { g_rel2 = gen; }
            __syncthreads();
        } else {
            BAR_WAIT();
        }

        // ---- phase 2: q = A p (smem j/k, global i/halo); dot p.q -> partial ----
        #pragma unroll
        for (int u = 0; u < 4; u++) {
            float4 pv = s_p[u*1024+tid];
            float p0 = pv.x, p1 = pv.y, p2 = pv.z, p3 = pv.w;
            float q0 = EPSD*p0, q1 = EPSD*p1, q2 = EPSD*p2, q3 = EPSD*p3;
            if (cxp != 0.f) { float c_ = cxp; float4 pn = g_p[base4 + 8580 + u]; ACC(pn); }
            if (cxm != 0.f) { float c_ = cxm; float4 pn = g_p[base4 - 8580 + u]; ACC(pn); }
            if (cyp != 0.f) {
                float c_ = cyp;
                float4 pn = (tid + 33 < NTHR) ? s_p[u*1024+tid+33] : g_p[base4 + 132 + u];
                ACC(pn);
            }
            if (cym != 0.f) {
                float c_ = cym;
                float4 pn = (tid >= 33) ? s_p[u*1024+tid-33] : g_p[base4 - 132 + u];
                ACC(pn);
            }
            if (czp != 0.f) {
                float c_ = czp;
                float4 pn = (tid + 1 < NTHR) ? s_p[u*1024+tid+1] : g_p[base4 + 4 + u];
                ACC(pn);
            }
            if (czm != 0.f) {
                float c_ = czm;
                float4 pn = (tid >= 1) ? s_p[u*1024+tid-1] : g_p[base4 - 4 + u];
                ACC(pn);
            }
            s_q[u*1024+tid] = make_float4(q0, q1, q2, q3);
            QUADRED(p0*q0, p1*q1, p2*q2, p3*q3, u);
        }
        CROSSRED(g_pqpart + bid*16);

        // ---- barrier B: last block computes alpha ----
        BAR_ARRIVE();
        if (s_last) {
            if (tid < 128) {
                int s = tid & 15, prt = tid >> 4;
                double acc = 0.0;
                for (int b = prt; b < NBLK; b += 8) acc += (double)g_pqpart[b*16 + s];
                s_dred[tid] = acc;
            }
            __syncthreads();
            if (tid < 16) {
                double pq = 0.0;
                #pragma unroll
                for (int w = 0; w < 8; w++) pq += s_dred[w*16 + tid];
                float a = g_froz[tid] ? 0.f : g_gam[tid] / (float)pq;
                g_ab[tid] = a;
                __threadfence();
            }
            __syncthreads();
            if (tid == 0) { g_rel2 = gen; }
            __syncthreads();
        } else {
            BAR_WAIT();
        }
        if (tid < 16) s_alpha[tid] = g_ab[tid];
        __syncthreads();

        // ---- phase 3: r -= alpha q ; x_rx += alpha p ; r.r -> partial ----
        #pragma unroll
        for (int u = 0; u < 4; u++) {
            float4 rv = s_r[u*1024+tid];
            float4 qv = s_q[u*1024+tid];
            rv.x = fmaf(-s_alpha[4*u+0], qv.x, rv.x);
            rv.y = fmaf(-s_alpha[4*u+1], qv.y, rv.y);
            rv.z = fmaf(-s_alpha[4*u+2], qv.z, rv.z);
            rv.w = fmaf(-s_alpha[4*u+3], qv.w, rv.w);
            s_r[u*1024+tid] = rv;
            QUADRED(rv.x*rv.x, rv.y*rv.y, rv.z*rv.z, rv.w*rv.w, u);
        }
        if (slot >= 0) {
            #pragma unroll
            for (int u = 0; u < 4; u++) {
                float4 pv = s_p[u*1024+tid];
                g_xsel[slot*16 + 4*u+0] += s_alpha[4*u+0] * pv.x;
                g_xsel[slot*16 + 4*u+1] += s_alpha[4*u+1] * pv.y;
                g_xsel[slot*16 + 4*u+2] += s_alpha[4*u+2] * pv.z;
                g_xsel[slot*16 + 4*u+3] += s_alpha[4*u+3] * pv.w;
            }
        }
        CROSSRED(g_g2part + bid*16);

        // ---- barrier C: last block computes beta/gamma/frozen ----
        BAR_ARRIVE();
        if (s_last) {
            if (tid < 128) {
                int s = tid & 15, prt = tid >> 4;
                double acc = 0.0;
                for (int b = prt; b < NBLK; b += 8) acc += (double)g_g2part[b*16 + s];
                s_dred[tid] = acc;
            }
            __syncthreads();
            if (tid < 16) {
                double gn = 0.0;
                #pragma unroll
                for (int w = 0; w < 8; w++) gn += s_dred[w*16 + tid];
                float gnf = (float)gn;
                float b = g_froz[tid] ? 0.f : gnf / g_gam[tid];
                g_gam[tid] = gnf;
                if (gn <= ATOL2) g_froz[tid] = 1;
                g_ab[16 + tid] = b;
                __threadfence();
            }
            __syncthreads();
            if (tid == 0) { g_rel2 = gen; }
            __syncthreads();
        } else {
            BAR_WAIT();
        }
        if (tid < 16) s_beta[tid] = g_ab[16 + tid];
        __syncthreads();
    }
}

// ---------------- loss ----------------
__global__ void k_loss(const float* __restrict__ infm, const float* __restrict__ start,
                       const float* __restrict__ ref, float* __restrict__ out) {
    __shared__ double sd[256];
    __shared__ double sm[256];
    int t = threadIdx.x;
    int s = t >> 4;                   // source index
    int r = t & 15;                   // receiver index
    float d = g_xsel[r*16 + s] - g_xsel[(16+r)*16 + s];
    float diff = d - ref[t];
    sd[t] = (double)diff * (double)diff;
    double lm = 0.0;
    for (int idx = t; idx < NACT; idx += 256) {
        float dd = infm[idx] - start[idx];
        lm += (double)dd * (double)dd;
    }
    sm[t] = lm;
    __syncthreads();
    for (int off = 128; off >= 1; off >>= 1) {
        if (t < off) { sd[t] += sd[t+off]; sm[t] += sm[t+off]; }
        __syncthreads();
    }
    if (t == 0) {
        float loss_data  = (float)(sd[0] / 256.0);
        float loss_model = (float)(sm[0] / (double)NACT);
        out[0] = loss_data;           // alpha = 0.0 -> total == loss_data
        out[1] = loss_data;
        out[2] = loss_model;
    }
}

// ---------------- launch ----------------
extern "C" void kernel_launch(void* const* d_in, const int* in_sizes, int n_in,
                              void* d_out, int out_size) {
    const float* infm  = (const float*)d_in[0];
    const float* start = (const float*)d_in[1];
    const float* dref  = (const float*)d_in[2];
    const int*   act   = (const int*)  d_in[3];
    const int*   sa    = (const int*)  d_in[4];
    const int*   sb    = (const int*)  d_in[5];
    const int*   rxm   = (const int*)  d_in[6];
    const int*   rxn   = (const int*)  d_in[7];
    float* out = (float*)d_out;

    static int attr_done = 0;
    if (!attr_done) {
        cudaFuncSetAttribute(k_persist, cudaFuncAttributeMaxDynamicSharedMemorySize, DSMEM);
        attr_done = 1;
    }

    k_init_sigma<<<(NCELLS+255)/256, 256>>>();
    k_scatter<<<(NACT+255)/256, 256>>>(act, infm);
    k_coeffs<<<(NCX+NCY+NCZ+255)/256, 256>>>();
    k_zero<<<(NNODES*4+255)/256, 256>>>();
    k_persist<<<NBLK, NTHR, DSMEM>>>(sa, sb, rxm, rxn);
    k_loss<<<1, 256>>>(infm, start, dref, out);
}

// round 8
// speedup vs baseline: 1.9565x; 1.0984x over previous
#include <cuda_runtime.h>

// ---------------- problem constants ----------------
#define NNODES 139425          // 65*65*33
#define NCELLS 131072          // 64*64*32
#define NACT   81920
#define EPSD   1.0e-7f
#define ATOL2  2.0e-12         // (1e-6)^2 * ||b||^2, ||b||^2 = 2
#define NCX 137280
#define NCY 137280
#define NCZ 135200
#define CG_ITERS 100
#define NBLK 148
#define NTHR 1024
#define DSMEM (3*4*1024*16)    // p, r, q tiles (float4): 196608 B

// ---------------- device scratch ----------------
__device__ float4 g_r[NNODES*4];       // exchanged vector: residual r
__device__ float  g_sigma[NCELLS];
__device__ float  g_cx[NCX];
__device__ float  g_cy[NCY];
__device__ float  g_cz[NCZ];
__device__ float  g_pqpart[NBLK*16];
__device__ float  g_g2part[NBLK*16];
__device__ float  g_xsel[32*16];
__device__ float  g_ab[32];            // alpha[0..15], beta[16..31]
__device__ float  g_gam[16];
__device__ int    g_froz[16];
__device__ unsigned g_cnt;
__device__ volatile unsigned g_rel2;

// ---------------- setup kernels ----------------
__global__ void k_init_sigma() {
    int t = blockIdx.x*blockDim.x + threadIdx.x;
    if (t < NCELLS) g_sigma[t] = 1.0e-8f;            // 1/AIR_RES
}

__global__ void k_scatter(const int* __restrict__ act, const float* __restrict__ model) {
    int t = blockIdx.x*blockDim.x + threadIdx.x;
    if (t < NACT) g_sigma[act[t]] = 1.0f / model[t];
}

__global__ void k_coeffs() {
    int t = blockIdx.x*blockDim.x + threadIdx.x;
    if (t < NCX) {
        int k = t % 33; int r = t / 33; int j = r % 65; int i = r / 65;
        float s = 0.f;
        for (int jj = j-1; jj <= j; ++jj)
            for (int kk = k-1; kk <= k; ++kk)
                if (jj >= 0 && jj < 64 && kk >= 0 && kk < 32)
                    s += g_sigma[(i*64 + jj)*32 + kk];
        g_cx[t] = 6.25f * s;                          // 0.25 * 25.0
    } else if (t < NCX + NCY) {
        int e = t - NCX;
        int k = e % 33; int r = e / 33; int j = r % 64; int i = r / 64;
        float s = 0.f;
        for (int ii = i-1; ii <= i; ++ii)
            for (int kk = k-1; kk <= k; ++kk)
                if (ii >= 0 && ii < 64 && kk >= 0 && kk < 32)
                    s += g_sigma[(ii*64 + j)*32 + kk];
        g_cy[e] = 6.25f * s;
    } else if (t < NCX + NCY + NCZ) {
        int e = t - NCX - NCY;
        int k = e % 32; int r = e / 32; int j = r % 65; int i = r / 65;
        float s = 0.f;
        for (int ii = i-1; ii <= i; ++ii)
            for (int jj = j-1; jj <= j; ++jj)
                if (ii >= 0 && ii < 64 && jj >= 0 && jj < 64)
                    s += g_sigma[(ii*64 + jj)*32 + k];
        g_cz[e] = 6.25f * s;
    }
}

// per-launch state reset (runs on every graph replay)
__global__ void k_zero() {
    int t = blockIdx.x*blockDim.x + threadIdx.x;
    if (t < NNODES*4) g_r[t] = make_float4(0.f,0.f,0.f,0.f);
    if (t < 32*16) g_xsel[t] = 0.f;
    if (t < 32) g_ab[t] = 0.f;
    if (t < 16) { g_gam[t] = 2.f; g_froz[t] = 0; }
}

// set r = b (separate kernel: ordering vs zero-fill via launch boundary)
__global__ void k_setb(const int* __restrict__ sa, const int* __restrict__ sb) {
    int s = threadIdx.x;
    if (s < 16) {
        float* rf = (float*)g_r;
        rf[sa[s]*16 + s]  = 1.0f;
        rf[sb[s]*16 + s] -= 1.0f;
    }
}

// warp-shuffle reduce 4 floats (one quad) -> s_red[wid*16 + 4u + c]
#define QUADRED(v0, v1, v2, v3, u)                                             \
    {                                                                          \
        float a0=(v0), a1=(v1), a2=(v2), a3=(v3);                              \
        a0 += __shfl_down_sync(0xffffffffu, a0, 16);                           \
        a1 += __shfl_down_sync(0xffffffffu, a1, 16);                           \
        a2 += __shfl_down_sync(0xffffffffu, a2, 16);                           \
        a3 += __shfl_down_sync(0xffffffffu, a3, 16);                           \
        a0 += __shfl_down_sync(0xffffffffu, a0, 8);                            \
        a1 += __shfl_down_sync(0xffffffffu, a1, 8);                            \
        a2 += __shfl_down_sync(0xffffffffu, a2, 8);                            \
        a3 += __shfl_down_sync(0xffffffffu, a3, 8);                            \
        a0 += __shfl_down_sync(0xffffffffu, a0, 4);                            \
        a1 += __shfl_down_sync(0xffffffffu, a1, 4);                            \
        a2 += __shfl_down_sync(0xffffffffu, a2, 4);                            \
        a3 += __shfl_down_sync(0xffffffffu, a3, 4);                            \
        a0 += __shfl_down_sync(0xffffffffu, a0, 2);                            \
        a1 += __shfl_down_sync(0xffffffffu, a1, 2);                            \
        a2 += __shfl_down_sync(0xffffffffu, a2, 2);                            \
        a3 += __shfl_down_sync(0xffffffffu, a3, 2);                            \
        a0 += __shfl_down_sync(0xffffffffu, a0, 1);                            \
        a1 += __shfl_down_sync(0xffffffffu, a1, 1);                            \
        a2 += __shfl_down_sync(0xffffffffu, a2, 1);                            \
        a3 += __shfl_down_sync(0xffffffffu, a3, 1);                            \
        if (lane == 0) {                                                       \
            s_red[wid*16 + 4*(u) + 0] = a0;                                    \
            s_red[wid*16 + 4*(u) + 1] = a1;                                    \
            s_red[wid*16 + 4*(u) + 2] = a2;                                    \
            s_red[wid*16 + 4*(u) + 3] = a3;                                    \
        }                                                                      \
    }

// cross-warp finish: sum s_red over 32 warps -> gout[0..15]
#define CROSSRED(gout)                                                         \
    {                                                                          \
        __syncthreads();                                                       \
        if (tid < 16) {                                                        \
            float acc = 0.f;                                                   \
            _Pragma("unroll")                                                  \
            for (int w = 0; w < 32; w++) acc += s_red[w*16 + tid];             \
            s_cross[tid] = acc;                                                \
        }                                                                      \
        __syncthreads();                                                       \
        if (tid == 0) {                                                        \
            float4* o = (float4*)(gout);                                       \
            const float4* c = (const float4*)s_cross;                          \
            o[0] = c[0]; o[1] = c[1]; o[2] = c[2]; o[3] = c[3];                \
        }                                                                      \
    }

// barrier arrive: counter-based; sets s_last in the last-arriving block
#define BAR_ARRIVE()                                                           \
    gen++;                                                                     \
    __syncthreads();                                                           \
    if (tid == 0) {                                                            \
        __threadfence();                                                       \
        unsigned old = atomicAdd(&g_cnt, 1u);                                  \
        s_last = (old == gen*NBLK - 1u) ? 1 : 0;                               \
    }                                                                          \
    __syncthreads();

#define BAR_WAIT()                                                             \
    if (tid == 0) {                                                            \
        while (g_rel2 < gen) { }                                               \
        __threadfence();                                                       \
    }                                                                          \
    __syncthreads();

// accumulate one neighbor quad into q0..q3 (stencil on r)
#define ACC(pn)                                                                \
    {                                                                          \
        q0 = fmaf(c_, p0 - (pn).x, q0);                                        \
        q1 = fmaf(c_, p1 - (pn).y, q1);                                        \
        q2 = fmaf(c_, p2 - (pn).z, q2);                                        \
        q3 = fmaf(c_, p3 - (pn).w, q3);                                        \
    }

// ---------------- persistent CG kernel (2 barriers / iteration) ----------------
__global__ void __launch_bounds__(NTHR, 1)
k_persist(const int* __restrict__ rxm, const int* __restrict__ rxn)
{
    extern __shared__ float4 s_dyn[];
    float4* s_p = s_dyn;               // [4][1024] p (local only)
    float4* s_r = s_dyn + 4096;        // [4][1024] r (exchanged via g_r)
    float4* s_q = s_dyn + 8192;        // [4][1024] q (local only)

    const int tid = threadIdx.x;
    const int bid = blockIdx.x;
    const int lane = tid & 31;
    const int wid  = tid >> 5;
    const int node = bid*NTHR + tid;
    const bool valid = node < NNODES;

    int base4 = 0;
    float cxp=0.f, cxm=0.f, cyp=0.f, cym=0.f, czp=0.f, czm=0.f;
    if (valid) {
        int k = node % 33;
        int ij = node / 33;
        int j = ij % 65;
        int i = ij / 65;
        base4 = node * 4;
        if (i < 64) cxp = g_cx[(i*65 + j)*33 + k];
        if (i > 0)  cxm = g_cx[((i-1)*65 + j)*33 + k];
        if (j < 64) cyp = g_cy[(i*64 + j)*33 + k];
        if (j > 0)  cym = g_cy[(i*64 + (j-1))*33 + k];
        if (k < 32) czp = g_cz[(i*65 + j)*32 + k];
        if (k > 0)  czm = g_cz[(i*65 + j)*32 + (k-1)];
    }

    // receiver-slot ownership (32 distinct nodes)
    int slot = -1;
    if (valid) {
        for (int r2 = 0; r2 < 16; r2++) {
            if (node == rxm[r2]) slot = r2;
            if (node == rxn[r2]) slot = 16 + r2;
        }
    }

    // init tiles: p = 0, q = 0, r from g_r (holds b, set by k_setb)
    {
        float4 z = make_float4(0.f,0.f,0.f,0.f);
        #pragma unroll
        for (int u = 0; u < 4; u++) {
            s_p[u*1024+tid] = z;
            s_q[u*1024+tid] = z;
            s_r[u*1024+tid] = valid ? g_r[base4+u] : z;
        }
    }

    __shared__ float  s_red[32*16];
    __shared__ float  s_cross[16];
    __shared__ double s_dred[128];
    __shared__ float  s_alpha[16], s_beta[16];
    __shared__ int    s_last;
    if (tid < 16) s_beta[tid] = 0.f;
    __syncthreads();

    unsigned gen = g_rel2;       // stable generation base from previous launch

    #pragma unroll 1
    for (int it = 0; it < CG_ITERS; ++it) {
        // ---- phase A: Ar stencil; q = Ar + beta*q_old; p = r + beta*p_old;
        //      partial p.q ----
        #pragma unroll
        for (int u = 0; u < 4; u++) {
            float4 rv = s_r[u*1024+tid];
            float p0 = rv.x, p1 = rv.y, p2 = rv.z, p3 = rv.w;   // r components
            float q0 = EPSD*p0, q1 = EPSD*p1, q2 = EPSD*p2, q3 = EPSD*p3;
            if (cxp != 0.f) { float c_ = cxp; float4 pn = g_r[base4 + 8580 + u]; ACC(pn); }
            if (cxm != 0.f) { float c_ = cxm; float4 pn = g_r[base4 - 8580 + u]; ACC(pn); }
            if (cyp != 0.f) {
                float c_ = cyp;
                float4 pn = (tid + 33 < NTHR) ? s_r[u*1024+tid+33] : g_r[base4 + 132 + u];
                ACC(pn);
            }
            if (cym != 0.f) {
                float c_ = cym;
                float4 pn = (tid >= 33) ? s_r[u*1024+tid-33] : g_r[base4 - 132 + u];
                ACC(pn);
            }
            if (czp != 0.f) {
                float c_ = czp;
                float4 pn = (tid + 1 < NTHR) ? s_r[u*1024+tid+1] : g_r[base4 + 4 + u];
                ACC(pn);
            }
            if (czm != 0.f) {
                float c_ = czm;
                float4 pn = (tid >= 1) ? s_r[u*1024+tid-1] : g_r[base4 - 4 + u];
                ACC(pn);
            }
            // q = Ar + beta*q_old ; p = r + beta*p_old
            float4 qo = s_q[u*1024+tid];
            float4 po = s_p[u*1024+tid];
            q0 = fmaf(s_beta[4*u+0], qo.x, q0);
            q1 = fmaf(s_beta[4*u+1], qo.y, q1);
            q2 = fmaf(s_beta[4*u+2], qo.z, q2);
            q3 = fmaf(s_beta[4*u+3], qo.w, q3);
            float n0 = fmaf(s_beta[4*u+0], po.x, p0);
            float n1 = fmaf(s_beta[4*u+1], po.y, p1);
            float n2 = fmaf(s_beta[4*u+2], po.z, p2);
            float n3 = fmaf(s_beta[4*u+3], po.w, p3);
            s_q[u*1024+tid] = make_float4(q0, q1, q2, q3);
            s_p[u*1024+tid] = make_float4(n0, n1, n2, n3);
            QUADRED(n0*q0, n1*q1, n2*q2, n3*q3, u);
        }
        CROSSRED(g_pqpart + bid*16);

        // ---- barrier B: last block computes alpha ----
        BAR_ARRIVE();
        if (s_last) {
            if (tid < 128) {
                int s = tid & 15, prt = tid >> 4;
                double acc = 0.0;
                for (int b = prt; b < NBLK; b += 8) acc += (double)g_pqpart[b*16 + s];
                s_dred[tid] = acc;
            }
            __syncthreads();
            if (tid < 16) {
                double pq = 0.0;
                #pragma unroll
                for (int w = 0; w < 8; w++) pq += s_dred[w*16 + tid];
                float a = g_froz[tid] ? 0.f : g_gam[tid] / (float)pq;
                g_ab[tid] = a;
                __threadfence();
            }
            __syncthreads();
            if (tid == 0) { g_rel2 = gen; }
            __syncthreads();
        } else {
            BAR_WAIT();
        }
        if (tid < 16) s_alpha[tid] = g_ab[tid];
        __syncthreads();

        // ---- phase B: r -= alpha q (smem + publish); x_rx += alpha p; r.r ----
        #pragma unroll
        for (int u = 0; u < 4; u++) {
            float4 rv = s_r[u*1024+tid];
            float4 qv = s_q[u*1024+tid];
            rv.x = fmaf(-s_alpha[4*u+0], qv.x, rv.x);
            rv.y = fmaf(-s_alpha[4*u+1], qv.y, rv.y);
            rv.z = fmaf(-s_alpha[4*u+2], qv.z, rv.z);
            rv.w = fmaf(-s_alpha[4*u+3], qv.w, rv.w);
            s_r[u*1024+tid] = rv;
            if (valid) g_r[base4+u] = rv;
            QUADRED(rv.x*rv.x, rv.y*rv.y, rv.z*rv.z, rv.w*rv.w, u);
        }
        if (slot >= 0) {
            #pragma unroll
            for (int u = 0; u < 4; u++) {
                float4 pv = s_p[u*1024+tid];
                g_xsel[slot*16 + 4*u+0] += s_alpha[4*u+0] * pv.x;
                g_xsel[slot*16 + 4*u+1] += s_alpha[4*u+1] * pv.y;
                g_xsel[slot*16 + 4*u+2] += s_alpha[4*u+2] * pv.z;
                g_xsel[slot*16 + 4*u+3] += s_alpha[4*u+3] * pv.w;
            }
        }
        CROSSRED(g_g2part + bid*16);

        // ---- barrier C: last block computes beta/gamma/frozen;
        //      also publishes r visibility for next phase A ----
        BAR_ARRIVE();
        if (s_last) {
            if (tid < 128) {
                int s = tid & 15, prt = tid >> 4;
                double acc = 0.0;
                for (int b = prt; b < NBLK; b += 8) acc += (double)g_g2part[b*16 + s];
                s_dred[tid] = acc;
            }
            __syncthreads();
            if (tid < 16) {
                double gn = 0.0;
                #pragma unroll
                for (int w = 0; w < 8; w++) gn += s_dred[w*16 + tid];
                float gnf = (float)gn;
                float b = g_froz[tid] ? 0.f : gnf / g_gam[tid];
                g_gam[tid] = gnf;
                if (gn <= ATOL2) g_froz[tid] = 1;
                g_ab[16 + tid] = b;
                __threadfence();
            }
            __syncthreads();
            if (tid == 0) { g_rel2 = gen; }
            __syncthreads();
        } else {
            BAR_WAIT();
        }
        if (tid < 16) s_beta[tid] = g_ab[16 + tid];
        __syncthreads();
    }
}

// ---------------- loss ----------------
__global__ void k_loss(const float* __restrict__ infm, const float* __restrict__ start,
                       const float* __restrict__ ref, float* __restrict__ out) {
    __shared__ double sd[256];
    __shared__ double sm[256];
    int t = threadIdx.x;
    int s = t >> 4;                   // source index
    int r = t & 15;                   // receiver index
    float d = g_xsel[r*16 + s] - g_xsel[(16+r)*16 + s];
    float diff = d - ref[t];
    sd[t] = (double)diff * (double)diff;
    double lm = 0.0;
    for (int idx = t; idx < NACT; idx += 256) {
        float dd = infm[idx] - start[idx];
        lm += (double)dd * (double)dd;
    }
    sm[t] = lm;
    __syncthreads();
    for (int off = 128; off >= 1; off >>= 1) {
        if (t < off) { sd[t] += sd[t+off]; sm[t] += sm[t+off]; }
        __syncthreads();
    }
    if (t == 0) {
        float loss_data  = (float)(sd[0] / 256.0);
        float loss_model = (float)(sm[0] / (double)NACT);
        out[0] = loss_data;           // alpha = 0.0 -> total == loss_data
        out[1] = loss_data;
        out[2] = loss_model;
    }
}

// ---------------- launch ----------------
extern "C" void kernel_launch(void* const* d_in, const int* in_sizes, int n_in,
                              void* d_out, int out_size) {
    const float* infm  = (const float*)d_in[0];
    const float* start = (const float*)d_in[1];
    const float* dref  = (const float*)d_in[2];
    const int*   act   = (const int*)  d_in[3];
    const int*   sa    = (const int*)  d_in[4];
    const int*   sb    = (const int*)  d_in[5];
    const int*   rxm   = (const int*)  d_in[6];
    const int*   rxn   = (const int*)  d_in[7];
    float* out = (float*)d_out;

    static int attr_done = 0;
    if (!attr_done) {
        cudaFuncSetAttribute(k_persist, cudaFuncAttributeMaxDynamicSharedMemorySize, DSMEM);
        attr_done = 1;
    }

    k_init_sigma<<<(NCELLS+255)/256, 256>>>();
    k_scatter<<<(NACT+255)/256, 256>>>(act, infm);
    k_coeffs<<<(NCX+NCY+NCZ+255)/256, 256>>>();
    k_zero<<<(NNODES*4+255)/256, 256>>>();
    k_setb<<<1, 32>>>(sa, sb);
    k_persist<<<NBLK, NTHR, DSMEM>>>(rxm, rxn);
    k_loss<<<1, 256>>>(infm, start, dref, out);
}

// round 10
// speedup vs baseline: 2.5494x; 1.3030x over previous
#include <cuda_runtime.h>

// ---------------- problem constants ----------------
#define NNODES 139425          // 65*65*33
#define NCELLS 131072          // 64*64*32
#define NACT   81920
#define EPSD   1.0e-7f
#define ATOL2  2.0e-12         // (1e-6)^2 * ||b||^2, ||b||^2 = 2
#define NCX 137280
#define NCY 137280
#define NCZ 135200
#define CG_ITERS 100
#define NBLK 137               // ceil(139425/1024)
#define NTHR 1024
#define DSMEM (3*4*1024*16)    // p, r, q tiles (float4): 196608 B

// ---------------- device scratch ----------------
__device__ float4 g_r[NNODES*4];       // exchanged vector: residual r
__device__ float  g_sigma[NCELLS];
__device__ float  g_cx[NCX];
__device__ float  g_cy[NCY];
__device__ float  g_cz[NCZ];
__device__ double g_dotA[16];          // p.q accumulators
__device__ double g_dotB[16];          // r.r accumulators
__device__ float  g_xsel[32*16];
__device__ float  g_ab[32];            // alpha[0..15], beta[16..31]
__device__ float  g_gam[16];
__device__ int    g_froz[16];
__device__ unsigned g_cnt;
__device__ volatile unsigned g_rel2;

// ---------------- setup kernels ----------------
__global__ void k_init_sigma() {
    int t = blockIdx.x*blockDim.x + threadIdx.x;
    if (t < NCELLS) g_sigma[t] = 1.0e-8f;            // 1/AIR_RES
}

__global__ void k_scatter(const int* __restrict__ act, const float* __restrict__ model) {
    int t = blockIdx.x*blockDim.x + threadIdx.x;
    if (t < NACT) g_sigma[act[t]] = 1.0f / model[t];
}

__global__ void k_coeffs() {
    int t = blockIdx.x*blockDim.x + threadIdx.x;
    if (t < NCX) {
        int k = t % 33; int r = t / 33; int j = r % 65; int i = r / 65;
        float s = 0.f;
        for (int jj = j-1; jj <= j; ++jj)
            for (int kk = k-1; kk <= k; ++kk)
                if (jj >= 0 && jj < 64 && kk >= 0 && kk < 32)
                    s += g_sigma[(i*64 + jj)*32 + kk];
        g_cx[t] = 6.25f * s;                          // 0.25 * 25.0
    } else if (t < NCX + NCY) {
        int e = t - NCX;
        int k = e % 33; int r = e / 33; int j = r % 64; int i = r / 64;
        float s = 0.f;
        for (int ii = i-1; ii <= i; ++ii)
            for (int kk = k-1; kk <= k; ++kk)
                if (ii >= 0 && ii < 64 && kk >= 0 && kk < 32)
                    s += g_sigma[(ii*64 + j)*32 + kk];
        g_cy[e] = 6.25f * s;
    } else if (t < NCX + NCY + NCZ) {
        int e = t - NCX - NCY;
        int k = e % 32; int r = e / 32; int j = r % 65; int i = r / 65;
        float s = 0.f;
        for (int ii = i-1; ii <= i; ++ii)
            for (int jj = j-1; jj <= j; ++jj)
                if (ii >= 0 && ii < 64 && jj >= 0 && jj < 64)
                    s += g_sigma[(ii*64 + jj)*32 + k];
        g_cz[e] = 6.25f * s;
    }
}

// per-launch state reset (runs on every graph replay)
__global__ void k_zero() {
    int t = blockIdx.x*blockDim.x + threadIdx.x;
    if (t < NNODES*4) g_r[t] = make_float4(0.f,0.f,0.f,0.f);
    if (t < 32*16) g_xsel[t] = 0.f;
    if (t < 32) g_ab[t] = 0.f;
    if (t < 16) {
        g_gam[t] = 2.f; g_froz[t] = 0;
        g_dotA[t] = 0.0; g_dotB[t] = 0.0;
    }
}

// set r = b (separate kernel: ordering vs zero-fill via launch boundary)
__global__ void k_setb(const int* __restrict__ sa, const int* __restrict__ sb) {
    int s = threadIdx.x;
    if (s < 16) {
        float* rf = (float*)g_r;
        rf[sa[s]*16 + s]  = 1.0f;
        rf[sb[s]*16 + s] -= 1.0f;
    }
}

// warp-shuffle reduce 4 floats (one quad) -> s_red[wid*16 + 4u + c]
#define QUADRED(v0, v1, v2, v3, u)                                             \
    {                                                                          \
        float a0=(v0), a1=(v1), a2=(v2), a3=(v3);                              \
        a0 += __shfl_down_sync(0xffffffffu, a0, 16);                           \
        a1 += __shfl_down_sync(0xffffffffu, a1, 16);                           \
        a2 += __shfl_down_sync(0xffffffffu, a2, 16);                           \
        a3 += __shfl_down_sync(0xffffffffu, a3, 16);                           \
        a0 += __shfl_down_sync(0xffffffffu, a0, 8);                            \
        a1 += __shfl_down_sync(0xffffffffu, a1, 8);                            \
        a2 += __shfl_down_sync(0xffffffffu, a2, 8);                            \
        a3 += __shfl_down_sync(0xffffffffu, a3, 8);                            \
        a0 += __shfl_down_sync(0xffffffffu, a0, 4);                            \
        a1 += __shfl_down_sync(0xffffffffu, a1, 4);                            \
        a2 += __shfl_down_sync(0xffffffffu, a2, 4);                            \
        a3 += __shfl_down_sync(0xffffffffu, a3, 4);                            \
        a0 += __shfl_down_sync(0xffffffffu, a0, 2);                            \
        a1 += __shfl_down_sync(0xffffffffu, a1, 2);                            \
        a2 += __shfl_down_sync(0xffffffffu, a2, 2);                            \
        a3 += __shfl_down_sync(0xffffffffu, a3, 2);                            \
        a0 += __shfl_down_sync(0xffffffffu, a0, 1);                            \
        a1 += __shfl_down_sync(0xffffffffu, a1, 1);                            \
        a2 += __shfl_down_sync(0xffffffffu, a2, 1);                            \
        a3 += __shfl_down_sync(0xffffffffu, a3, 1);                            \
        if (lane == 0) {                                                       \
            s_red[wid*16 + 4*(u) + 0] = a0;                                    \
            s_red[wid*16 + 4*(u) + 1] = a1;                                    \
            s_red[wid*16 + 4*(u) + 2] = a2;                                    \
            s_red[wid*16 + 4*(u) + 3] = a3;                                    \
        }                                                                      \
    }

// cross-warp finish + atomic publish into 16 doubles
#define PUBRED(gdst)                                                           \
    {                                                                          \
        __syncthreads();                                                       \
        if (tid < 16) {                                                        \
            float acc = 0.f;                                                   \
            _Pragma("unroll")                                                  \
            for (int w = 0; w < 32; w++) acc += s_red[w*16 + tid];             \
            atomicAdd(&(gdst)[tid], (double)acc);                              \
        }                                                                      \
    }

// barrier arrive: counter-based; sets s_last in the last-arriving block
#define BAR_ARRIVE()                                                           \
    gen++;                                                                     \
    __syncthreads();                                                           \
    if (tid == 0) {                                                            \
        __threadfence();                                                       \
        unsigned old = atomicAdd(&g_cnt, 1u);                                  \
        s_last = (old == gen*NBLK - 1u) ? 1 : 0;                               \
    }                                                                          \
    __syncthreads();

#define BAR_WAIT()                                                             \
    if (tid == 0) {                                                            \
        while (g_rel2 < gen) { }                                               \
        __threadfence();                                                       \
    }                                                                          \
    __syncthreads();

// accumulate one neighbor quad into q0..q3 (stencil on p)
#define ACC(pn)                                                                \
    {                                                                          \
        q0 = fmaf(c_, p0 - (pn).x, q0);                                        \
        q1 = fmaf(c_, p1 - (pn).y, q1);                                        \
        q2 = fmaf(c_, p2 - (pn).z, q2);                                        \
        q3 = fmaf(c_, p3 - (pn).w, q3);                                        \
    }

// ---------------- persistent CG kernel (2 barriers / iteration) ----------------
__global__ void __launch_bounds__(NTHR, 1)
k_persist(const int* __restrict__ rxm, const int* __restrict__ rxn)
{
    extern __shared__ float4 s_dyn[];
    float4* s_p = s_dyn;               // [4][1024] p (local only)
    float4* s_r = s_dyn + 4096;        // [4][1024] r (exchanged via g_r)
    float4* s_q = s_dyn + 8192;        // [4][1024] q (local only)

    const int tid = threadIdx.x;
    const int lane = tid & 31;
    const int wid  = tid >> 5;
    const int node = blockIdx.x*NTHR + tid;
    const bool valid = node < NNODES;

    int base4 = 0;
    float cxp=0.f, cxm=0.f, cyp=0.f, cym=0.f, czp=0.f, czm=0.f;
    if (valid) {
        int k = node % 33;
        int ij = node / 33;
        int j = ij % 65;
        int i = ij / 65;
        base4 = node * 4;
        if (i < 64) cxp = g_cx[(i*65 + j)*33 + k];
        if (i > 0)  cxm = g_cx[((i-1)*65 + j)*33 + k];
        if (j < 64) cyp = g_cy[(i*64 + j)*33 + k];
        if (j > 0)  cym = g_cy[(i*64 + (j-1))*33 + k];
        if (k < 32) czp = g_cz[(i*65 + j)*32 + k];
        if (k > 0)  czm = g_cz[(i*65 + j)*32 + (k-1)];
    }

    // receiver-slot ownership (32 distinct nodes)
    int slot = -1;
    if (valid) {
        for (int r2 = 0; r2 < 16; r2++) {
            if (node == rxm[r2]) slot = r2;
            if (node == rxn[r2]) slot = 16 + r2;
        }
    }

    // init tiles: p = 0, q = 0, r from g_r (holds b, set by k_setb)
    {
        float4 z = make_float4(0.f,0.f,0.f,0.f);
        #pragma unroll
        for (int u = 0; u < 4; u++) {
            s_p[u*1024+tid] = z;
            s_q[u*1024+tid] = z;
            s_r[u*1024+tid] = valid ? g_r[base4+u] : z;
        }
    }

    __shared__ float  s_red[32*16];
    __shared__ float  s_alpha[16], s_beta[16];
    __shared__ int    s_last;
    if (tid < 16) s_beta[tid] = 0.f;
    __syncthreads();

    unsigned gen = g_rel2;       // stable generation base from previous launch

    #pragma unroll 1
    for (int it = 0; it < CG_ITERS; ++it) {
        // ---- phase A: Ar stencil; q = Ar + beta*q_old; p = r + beta*p_old;
        //      partial p.q ----
        #pragma unroll
        for (int u = 0; u < 4; u++) {
            float4 rv = s_r[u*1024+tid];
            float p0 = rv.x, p1 = rv.y, p2 = rv.z, p3 = rv.w;   // r components
            float q0 = EPSD*p0, q1 = EPSD*p1, q2 = EPSD*p2, q3 = EPSD*p3;
            if (cxp != 0.f) { float c_ = cxp; float4 pn = g_r[base4 + 8580 + u]; ACC(pn); }
            if (cxm != 0.f) { float c_ = cxm; float4 pn = g_r[base4 - 8580 + u]; ACC(pn); }
            if (cyp != 0.f) {
                float c_ = cyp;
                float4 pn = (tid + 33 < NTHR) ? s_r[u*1024+tid+33] : g_r[base4 + 132 + u];
                ACC(pn);
            }
            if (cym != 0.f) {
                float c_ = cym;
                float4 pn = (tid >= 33) ? s_r[u*1024+tid-33] : g_r[base4 - 132 + u];
                ACC(pn);
            }
            if (czp != 0.f) {
                float c_ = czp;
                float4 pn = (tid + 1 < NTHR) ? s_r[u*1024+tid+1] : g_r[base4 + 4 + u];
                ACC(pn);
            }
            if (czm != 0.f) {
                float c_ = czm;
                float4 pn = (tid >= 1) ? s_r[u*1024+tid-1] : g_r[base4 - 4 + u];
                ACC(pn);
            }
            // q = Ar + beta*q_old ; p = r + beta*p_old
            float4 qo = s_q[u*1024+tid];
            float4 po = s_p[u*1024+tid];
            q0 = fmaf(s_beta[4*u+0], qo.x, q0);
            q1 = fmaf(s_beta[4*u+1], qo.y, q1);
            q2 = fmaf(s_beta[4*u+2], qo.z, q2);
            q3 = fmaf(s_beta[4*u+3], qo.w, q3);
            float n0 = fmaf(s_beta[4*u+0], po.x, p0);
            float n1 = fmaf(s_beta[4*u+1], po.y, p1);
            float n2 = fmaf(s_beta[4*u+2], po.z, p2);
            float n3 = fmaf(s_beta[4*u+3], po.w, p3);
            s_q[u*1024+tid] = make_float4(q0, q1, q2, q3);
            s_p[u*1024+tid] = make_float4(n0, n1, n2, n3);
            QUADRED(n0*q0, n1*q1, n2*q2, n3*q3, u);
        }
        PUBRED(g_dotA);

        // ---- barrier B: last block computes alpha from g_dotA ----
        BAR_ARRIVE();
        if (s_last) {
            if (tid < 16) {
                double pq = g_dotA[tid];
                float a = g_froz[tid] ? 0.f : g_gam[tid] / (float)pq;
                g_ab[tid] = a;
                g_dotA[tid] = 0.0;
                __threadfence();
            }
            __syncthreads();
            if (tid == 0) { g_rel2 = gen; }
            __syncthreads();
        } else {
            BAR_WAIT();
        }
        if (tid < 16) s_alpha[tid] = g_ab[tid];
        __syncthreads();

        // ---- phase B: r -= alpha q (smem + publish); x_rx += alpha p; r.r ----
        #pragma unroll
        for (int u = 0; u < 4; u++) {
            float4 rv = s_r[u*1024+tid];
            float4 qv = s_q[u*1024+tid];
            rv.x = fmaf(-s_alpha[4*u+0], qv.x, rv.x);
            rv.y = fmaf(-s_alpha[4*u+1], qv.y, rv.y);
            rv.z = fmaf(-s_alpha[4*u+2], qv.z, rv.z);
            rv.w = fmaf(-s_alpha[4*u+3], qv.w, rv.w);
            s_r[u*1024+tid] = rv;
            if (valid) g_r[base4+u] = rv;
            QUADRED(rv.x*rv.x, rv.y*rv.y, rv.z*rv.z, rv.w*rv.w, u);
        }
        if (slot >= 0) {
            #pragma unroll
            for (int u = 0; u < 4; u++) {
                float4 pv = s_p[u*1024+tid];
                g_xsel[slot*16 + 4*u+0] += s_alpha[4*u+0] * pv.x;
                g_xsel[slot*16 + 4*u+1] += s_alpha[4*u+1] * pv.y;
                g_xsel[slot*16 + 4*u+2] += s_alpha[4*u+2] * pv.z;
                g_xsel[slot*16 + 4*u+3] += s_alpha[4*u+3] * pv.w;
            }
        }
        PUBRED(g_dotB);

        // ---- barrier C: last block computes beta/gamma/frozen;
        //      also publishes r visibility for next phase A ----
        BAR_ARRIVE();
        if (s_last) {
            if (tid < 16) {
                double gn = g_dotB[tid];
                float gnf = (float)gn;
                float b = g_froz[tid] ? 0.f : gnf / g_gam[tid];
                g_gam[tid] = gnf;
                if (gn <= ATOL2) g_froz[tid] = 1;
                g_ab[16 + tid] = b;
                g_dotB[tid] = 0.0;
                __threadfence();
            }
            __syncthreads();
            if (tid == 0) { g_rel2 = gen; }
            __syncthreads();
        } else {
            BAR_WAIT();
        }
        if (tid < 16) s_beta[tid] = g_ab[16 + tid];
        __syncthreads();
    }
}

// ---------------- loss ----------------
__global__ void k_loss(const float* __restrict__ infm, const float* __restrict__ start,
                       const float* __restrict__ ref, float* __restrict__ out) {
    __shared__ double sd[256];
    __shared__ double sm[256];
    int t = threadIdx.x;
    int s = t >> 4;                   // source index
    int r = t & 15;                   // receiver index
    float d = g_xsel[r*16 + s] - g_xsel[(16+r)*16 + s];
    float diff = d - ref[t];
    sd[t] = (double)diff * (double)diff;
    double lm = 0.0;
    for (int idx = t; idx < NACT; idx += 256) {
        float dd = infm[idx] - start[idx];
        lm += (double)dd * (double)dd;
    }
    sm[t] = lm;
    __syncthreads();
    for (int off = 128; off >= 1; off >>= 1) {
        if (t < off) { sd[t] += sd[t+off]; sm[t] += sm[t+off]; }
        __syncthreads();
    }
    if (t == 0) {
        float loss_data  = (float)(sd[0] / 256.0);
        float loss_model = (float)(sm[0] / (double)NACT);
        out[0] = loss_data;           // alpha = 0.0 -> total == loss_data
        out[1] = loss_data;
        out[2] = loss_model;
    }
}

// ---------------- launch ----------------
extern "C" void kernel_launch(void* const* d_in, const int* in_sizes, int n_in,
                              void* d_out, int out_size) {
    const float* infm  = (const float*)d_in[0];
    const float* start = (const float*)d_in[1];
    const float* dref  = (const float*)d_in[2];
    const int*   act   = (const int*)  d_in[3];
    const int*   sa    = (const int*)  d_in[4];
    const int*   sb    = (const int*)  d_in[5];
    const int*   rxm   = (const int*)  d_in[6];
    const int*   rxn   = (const int*)  d_in[7];
    float* out = (float*)d_out;

    static int attr_done = 0;
    if (!attr_done) {
        cudaFuncSetAttribute(k_persist, cudaFuncAttributeMaxDynamicSharedMemorySize, DSMEM);
        attr_done = 1;
    }

    k_init_sigma<<<(NCELLS+255)/256, 256>>>();
    k_scatter<<<(NACT+255)/256, 256>>>(act, infm);
    k_coeffs<<<(NCX+NCY+NCZ+255)/256, 256>>>();
    k_zero<<<(NNODES*4+255)/256, 256>>>();
    k_setb<<<1, 32>>>(sa, sb);
    k_persist<<<NBLK, NTHR, DSMEM>>>(rxm, rxn);
    k_loss<<<1, 256>>>(infm, start, dref, out);
}